// round 13
// baseline (speedup 1.0000x reference)
#include <cuda_runtime.h>
#include <math.h>
#include <stdint.h>

#define LQ 4096
#define NC 64
#define CLEN 64
#define PSTR 72

__device__ float g_feat[4*128*4096];
__device__ float g_pvterm[4*4096];
__device__ float g_casum[4*128];
__device__ float g_ca[4*128];
__device__ float g_scores[4*4096];
__device__ int   g_order[4*4096];
__device__ float g_xT[4*4096*128];
__device__ float g_x1n[4*4096*128];
__device__ float g_xz[4*4096*512];
__device__ float g_xc[4*4096*256];
__device__ float g_dbc[4*4096*40];
__device__ float g_dt[4*4096*256];
__device__ float g_cP[4*256*NC*16];
__device__ float g_cE[4*256*NC*16];
__device__ float g_hinit[4*256*NC*16];
__device__ float g_y[4*4096*256];

__device__ __forceinline__ float sigmf(float x){ return 1.f/(1.f+__expf(-x)); }
__device__ __forceinline__ float geluf(float x){ return 0.5f*x*(1.f+erff(x*0.70710678f)); }
__device__ __forceinline__ float warp_sum(float v){
    v += __shfl_xor_sync(~0u,v,16); v += __shfl_xor_sync(~0u,v,8);
    v += __shfl_xor_sync(~0u,v,4);  v += __shfl_xor_sync(~0u,v,2);
    v += __shfl_xor_sync(~0u,v,1);  return v;
}
__device__ __forceinline__ uint32_t f2tf(float f){
    uint32_t r; asm("cvt.rna.tf32.f32 %0, %1;" : "=r"(r) : "f"(f)); return r;
}

// zero the border cells of the 66-row x PSTR plane (logical cols 3..68 used)
__device__ __forceinline__ void zero_border(float* pl, int tid){
    for(int i=tid;i<260;i+=256){
        int idx;
        if(i<66) idx=3+i;                       // top row
        else if(i<132) idx=65*PSTR+3+(i-66);    // bottom row
        else if(i<196) idx=(i-131)*PSTR+3;      // left col rows 1..64
        else idx=(i-195)*PSTR+68;               // right col rows 1..64
        pl[idx]=0.f;
    }
}

// pv term + zero score accumulator: 2 threads per pixel (64 channels each)
__global__ void k_pv(const float* __restrict__ x, float* __restrict__ pv,
                     float* __restrict__ sacc){
    int gid = blockIdx.x*256+threadIdx.x;     // 32768
    int p = gid>>1, half = gid&1;
    int b = p>>12, hw = p&4095;
    const float* xp = x + (size_t)b*128*LQ + (size_t)half*64*LQ + hw;
    float s=0.f,s2=0.f;
    #pragma unroll 8
    for(int c=0;c<64;c++){ float v=xp[c*LQ]; s+=v; s2+=v*v; }
    s += __shfl_xor_sync(~0u,s,1);
    s2 += __shfl_xor_sync(~0u,s2,1);
    if(half==0){
        float var = (s2 - s*s*(1.f/128.f))*(1.f/127.f);
        pv[p] = 0.3f*sigmf(10.f*var);
        sacc[p] = 0.f;
    }
}

__global__ __launch_bounds__(256) void k_conv1(const float* __restrict__ x,
        const float* __restrict__ w_, const float* __restrict__ b_,
        float* __restrict__ feat, float* __restrict__ casum){
    __shared__ float pl[66*PSTR]; __shared__ float rs[8];
    int bc = blockIdx.x, c = bc&127, tid = threadIdx.x;
    const float* xp = x + (size_t)bc*4096;
    zero_border(pl, tid);
    for(int i=tid;i<1024;i+=256){
        int h=i>>4, w4=(i&15)*4;
        *(float4*)&pl[(h+1)*PSTR+4+w4] = ((const float4*)xp)[i];
    }
    float w[9];
    #pragma unroll
    for(int q=0;q<9;q++) w[q]=w_[c*9+q];
    float bias=b_[c];
    __syncthreads();
    float lsum=0.f;
    #pragma unroll 4
    for(int i=0;i<16;i++){
        int p=tid+i*256, h=p>>6, ww=p&63;
        const float* bp=&pl[h*PSTR+3+ww];
        float s=bias
          + w[0]*bp[0]       + w[1]*bp[1]       + w[2]*bp[2]
          + w[3]*bp[PSTR]    + w[4]*bp[PSTR+1]  + w[5]*bp[PSTR+2]
          + w[6]*bp[2*PSTR]  + w[7]*bp[2*PSTR+1]+ w[8]*bp[2*PSTR+2];
        float g=geluf(s);
        feat[(size_t)bc*4096+p]=g; lsum+=g;
    }
    lsum=warp_sum(lsum);
    if((tid&31)==0) rs[tid>>5]=lsum;
    __syncthreads();
    if(tid==0){ float t=0.f; for(int q=0;q<8;q++) t+=rs[q]; casum[bc]=t; }
}

__global__ void k_ca(const float* __restrict__ casum, const float* __restrict__ w1,
                     const float* __restrict__ w2, float* __restrict__ ca){
    __shared__ float mean[4][128]; __shared__ float hid[4][32];
    int tid=threadIdx.x;
    for(int i=0;i<4;i++) mean[i][tid]=casum[i*128+tid]*(1.f/4096.f);
    __syncthreads();
    int b=tid>>5, j=tid&31;
    float h=0.f;
    for(int c=0;c<128;c++) h += mean[b][c]*w1[j*128+c];
    hid[b][j]=fmaxf(h,0.f);
    __syncthreads();
    for(int b2=0;b2<4;b2++){
        float v=0.f;
        #pragma unroll
        for(int j2=0;j2<32;j2++) v += hid[b2][j2]*w2[tid*32+j2];
        ca[b2*128+tid]=sigmf(v);
    }
}

__global__ __launch_bounds__(256) void k_score2(const float* __restrict__ feat,
        const float* __restrict__ ca, const float* __restrict__ w2_,
        const float* __restrict__ b2_, const float* __restrict__ hw_,
        float* __restrict__ sacc){
    __shared__ float pl[66*PSTR];
    int bc=blockIdx.x, b=bc>>7, c=bc&127, tid=threadIdx.x;
    const float* fp=feat+(size_t)bc*4096;
    zero_border(pl, tid);
    for(int i=tid;i<1024;i+=256){
        int h=i>>4, w4=(i&15)*4;
        *(float4*)&pl[(h+1)*PSTR+4+w4] = ((const float4*)fp)[i];
    }
    float w[9];
    #pragma unroll
    for(int q=0;q<9;q++) w[q]=w2_[c*9+q];
    float cav=ca[bc], bias=b2_[c], hwc=hw_[c];
    __syncthreads();
    #pragma unroll 4
    for(int i=0;i<16;i++){
        int p=tid+i*256, h=p>>6, ww=p&63;
        const float* bp=&pl[h*PSTR+3+ww];
        float s=
            w[0]*bp[0]       + w[1]*bp[1]       + w[2]*bp[2]
          + w[3]*bp[PSTR]    + w[4]*bp[PSTR+1]  + w[5]*bp[PSTR+2]
          + w[6]*bp[2*PSTR]  + w[7]*bp[2*PSTR+1]+ w[8]*bp[2*PSTR+2];
        float v = cav*s + bias;
        atomicAdd(&sacc[b*4096+p], geluf(v)*hwc);
    }
}

__global__ void k_sort(const float* __restrict__ sacc, const float* __restrict__ pv,
                       const float* __restrict__ hb_, int* __restrict__ order){
    __shared__ float sm[256];
    int b=blockIdx.x, p=threadIdx.x, py=p>>4, px=p&15;
    float hb0=hb_[0];
    float s=0.f;
    #pragma unroll
    for(int r=0;r<4;r++)
        #pragma unroll
        for(int cx=0;cx<4;cx++){
            int pix=(py*4+r)*64+px*4+cx;
            s += 0.7f*sigmf(sacc[b*4096+pix]+hb0) + pv[b*4096+pix];
        }
    sm[p]=s;
    __syncthreads();
    float mys=sm[p]; int rank=0;
    for(int j=0;j<256;j++){ float o=sm[j]; rank += (o>mys)||(o==mys && j<p); }
    #pragma unroll
    for(int j=0;j<16;j++){
        int pix=(py*4+(j>>2))*64 + px*4 + (j&3);
        order[b*4096+rank*16+j]=pix;
    }
}

__global__ void k_transpose(const float* __restrict__ x, float* __restrict__ xT){
    __shared__ float tile[32][33];
    int b=blockIdx.z, c0=blockIdx.y*32, p0=blockIdx.x*32;
    int tx=threadIdx.x, ty=threadIdx.y;
    for(int i=0;i<32;i+=8)
        tile[ty+i][tx] = x[((size_t)(b*128+c0+ty+i))*4096 + p0+tx];
    __syncthreads();
    for(int i=0;i<32;i+=8)
        xT[((size_t)(b*4096+p0+ty+i))*128 + c0+tx] = tile[tx][ty+i];
}

__global__ __launch_bounds__(256) void k_gather_ln(const float* __restrict__ xT,
        const float* __restrict__ pe, const int* __restrict__ order,
        const float* __restrict__ g_, const float* __restrict__ bn_,
        float* __restrict__ out){
    int warp=threadIdx.x>>5, lane=threadIdx.x&31;
    int token=blockIdx.x*8+warp, b=token>>12;
    int pix=order[token];
    float4 v=*(const float4*)&xT[((size_t)(b*4096+pix))*128+lane*4];
    float4 p=*(const float4*)&pe[pix*128+lane*4];
    v.x+=p.x; v.y+=p.y; v.z+=p.z; v.w+=p.w;
    float s=v.x+v.y+v.z+v.w;
    float s2=v.x*v.x+v.y*v.y+v.z*v.z+v.w*v.w;
    s=warp_sum(s); s2=warp_sum(s2);
    float mu=s*(1.f/128.f);
    float rstd=rsqrtf(s2*(1.f/128.f)-mu*mu+1e-5f);
    float4 g4=*(const float4*)&g_[lane*4];
    float4 b4=*(const float4*)&bn_[lane*4];
    float4 o;
    o.x=(v.x-mu)*rstd*g4.x+b4.x; o.y=(v.y-mu)*rstd*g4.y+b4.y;
    o.z=(v.z-mu)*rstd*g4.z+b4.z; o.w=(v.w-mu)*rstd*g4.w+b4.w;
    *(float4*)&out[(size_t)token*128+lane*4]=o;
}

#define GSTR 140
__global__ __launch_bounds__(256) void gemm_tf32(const float* __restrict__ A,
        const float* __restrict__ Bw, float* __restrict__ C, int M,int N,int K,
        int silu_from, const int* __restrict__ ord, int do_scatter){
    __shared__ uint32_t As[2][16][GSTR];
    __shared__ uint32_t Bs[2][16][GSTR];
    const int bm=blockIdx.y*128, bn=blockIdx.x*128;
    const int tid=threadIdx.x, lane=tid&31, warp=tid>>5;
    const int wm=(warp&1)*64, wn=(warp>>1)*32;
    const int g=lane>>2, tg=lane&3;
    const int lr=tid>>2, lq=(tid&3)*4;
    float acc[4][4][4];
    #pragma unroll
    for(int i=0;i<4;i++)
        #pragma unroll
        for(int j=0;j<4;j++)
            #pragma unroll
            for(int q=0;q<4;q++) acc[i][j][q]=0.f;
    const float* Ag = A + (size_t)(bm+lr)*K + lq;
    const float* Bg = Bw + (size_t)(bn+lr)*K + lq;
    const size_t sk64 = (size_t)64*K;
    float4 ra0,ra1,rb0,rb1;
    ra0=*(const float4*)(Ag); ra1=*(const float4*)(Ag+sk64);
    rb0=*(const float4*)(Bg); rb1=*(const float4*)(Bg+sk64);
    {
        As[0][lq+0][lr]=f2tf(ra0.x); As[0][lq+1][lr]=f2tf(ra0.y);
        As[0][lq+2][lr]=f2tf(ra0.z); As[0][lq+3][lr]=f2tf(ra0.w);
        As[0][lq+0][lr+64]=f2tf(ra1.x); As[0][lq+1][lr+64]=f2tf(ra1.y);
        As[0][lq+2][lr+64]=f2tf(ra1.z); As[0][lq+3][lr+64]=f2tf(ra1.w);
        Bs[0][lq+0][lr]=f2tf(rb0.x); Bs[0][lq+1][lr]=f2tf(rb0.y);
        Bs[0][lq+2][lr]=f2tf(rb0.z); Bs[0][lq+3][lr]=f2tf(rb0.w);
        Bs[0][lq+0][lr+64]=f2tf(rb1.x); Bs[0][lq+1][lr+64]=f2tf(rb1.y);
        Bs[0][lq+2][lr+64]=f2tf(rb1.z); Bs[0][lq+3][lr+64]=f2tf(rb1.w);
    }
    __syncthreads();
    const int nk=K>>4;
    for(int kt=0;kt<nk;kt++){
        const int cur=kt&1;
        if(kt+1<nk){
            ra0=*(const float4*)(Ag+(kt+1)*16);
            ra1=*(const float4*)(Ag+sk64+(kt+1)*16);
            rb0=*(const float4*)(Bg+(kt+1)*16);
            rb1=*(const float4*)(Bg+sk64+(kt+1)*16);
        }
        #pragma unroll
        for(int ks=0;ks<2;ks++){
            uint32_t af[4][4], bf[4][2];
            #pragma unroll
            for(int i=0;i<4;i++){
                int row=wm+16*i+g;
                af[i][0]=As[cur][ks*8+tg][row];
                af[i][1]=As[cur][ks*8+tg][row+8];
                af[i][2]=As[cur][ks*8+tg+4][row];
                af[i][3]=As[cur][ks*8+tg+4][row+8];
            }
            #pragma unroll
            for(int j=0;j<4;j++){
                int col=wn+8*j+g;
                bf[j][0]=Bs[cur][ks*8+tg][col];
                bf[j][1]=Bs[cur][ks*8+tg+4][col];
            }
            #pragma unroll
            for(int i=0;i<4;i++)
                #pragma unroll
                for(int j=0;j<4;j++){
                    asm volatile(
                      "mma.sync.aligned.m16n8k8.row.col.f32.tf32.tf32.f32 "
                      "{%0,%1,%2,%3},{%4,%5,%6,%7},{%8,%9},{%0,%1,%2,%3};"
                      : "+f"(acc[i][j][0]),"+f"(acc[i][j][1]),
                        "+f"(acc[i][j][2]),"+f"(acc[i][j][3])
                      : "r"(af[i][0]),"r"(af[i][1]),"r"(af[i][2]),"r"(af[i][3]),
                        "r"(bf[j][0]),"r"(bf[j][1]));
                }
        }
        if(kt+1<nk){
            const int nb=(kt+1)&1;
            As[nb][lq+0][lr]=f2tf(ra0.x); As[nb][lq+1][lr]=f2tf(ra0.y);
            As[nb][lq+2][lr]=f2tf(ra0.z); As[nb][lq+3][lr]=f2tf(ra0.w);
            As[nb][lq+0][lr+64]=f2tf(ra1.x); As[nb][lq+1][lr+64]=f2tf(ra1.y);
            As[nb][lq+2][lr+64]=f2tf(ra1.z); As[nb][lq+3][lr+64]=f2tf(ra1.w);
            Bs[nb][lq+0][lr]=f2tf(rb0.x); Bs[nb][lq+1][lr]=f2tf(rb0.y);
            Bs[nb][lq+2][lr]=f2tf(rb0.z); Bs[nb][lq+3][lr]=f2tf(rb0.w);
            Bs[nb][lq+0][lr+64]=f2tf(rb1.x); Bs[nb][lq+1][lr+64]=f2tf(rb1.y);
            Bs[nb][lq+2][lr+64]=f2tf(rb1.z); Bs[nb][lq+3][lr+64]=f2tf(rb1.w);
        }
        __syncthreads();
    }
    if(do_scatter){
        #pragma unroll
        for(int i=0;i<4;i++){
            int row=bm+wm+16*i+g;
            int b=row>>12;
            int p1=ord[row], p2=ord[row+8];
            #pragma unroll
            for(int j=0;j<4;j++){
                int col=bn+wn+8*j+2*tg;
                float* o1=C+((size_t)(b*128+col))*4096;
                float* o2=C+((size_t)(b*128+col+1))*4096;
                o1[p1]=acc[i][j][0]; o2[p1]=acc[i][j][1];
                o1[p2]=acc[i][j][2]; o2[p2]=acc[i][j][3];
            }
        }
    }else{
        #pragma unroll
        for(int i=0;i<4;i++)
            #pragma unroll
            for(int j=0;j<4;j++){
                int row=bm+wm+16*i+g, col=bn+wn+8*j+2*tg;
                float4 o=make_float4(acc[i][j][0],acc[i][j][1],acc[i][j][2],acc[i][j][3]);
                if(col>=silu_from){
                    o.x*=sigmf(o.x); o.y*=sigmf(o.y);
                    o.z*=sigmf(o.z); o.w*=sigmf(o.w);
                }
                float* cp=C+(size_t)row*N+col;
                *(float2*)cp = make_float2(o.x,o.y);
                *(float2*)(cp+(size_t)8*N) = make_float2(o.z,o.w);
            }
    }
}

#define XSTR 260
extern __shared__ float smemx[];
__global__ __launch_bounds__(256) void k_xproj(const float* __restrict__ xz,
        const float* __restrict__ cw, const float* __restrict__ cb,
        const float* __restrict__ xpw, const float* __restrict__ dpw,
        const float* __restrict__ dpb, float* __restrict__ xcg,
        float* __restrict__ dbc, float* __restrict__ dtout){
    float* Ws = smemx;
    float* Xm = smemx + 40*XSTR;
    float* dpws = smemx + 75*XSTR;
    float* dtl  = dpws + 2048;
    int tid=threadIdx.x, tok0=blockIdx.x*32;
    int l0=tok0&4095;
    for(int i=tid;i<2560;i+=256){
        int r=i>>6, c4=(i&63)<<2;
        float4 v=*(const float4*)&xpw[r*256+c4];
        float* dst=&Ws[r*XSTR+c4];
        dst[0]=v.x; dst[1]=v.y; dst[2]=v.z; dst[3]=v.w;
    }
    for(int i=tid;i<2240;i+=256){
        int r=i>>6, c4=(i&63)<<2;
        float4 v=make_float4(0.f,0.f,0.f,0.f);
        if(l0+r>=3) v=*(const float4*)&xz[((size_t)(tok0-3+r))*512+c4];
        float* dst=&Xm[r*XSTR+c4];
        dst[0]=v.x; dst[1]=v.y; dst[2]=v.z; dst[3]=v.w;
    }
    for(int i=tid;i<2048;i+=256) dpws[i]=dpw[i];
    __syncthreads();
    {
        int c=tid;
        float4 wv=*(const float4*)&cw[c*4];
        float bias=cb[c];
        float xm0=Xm[0*XSTR+c], xm1=Xm[1*XSTR+c], xm2=Xm[2*XSTR+c];
        float xcr[32];
        #pragma unroll
        for(int t=0;t<32;t++){
            float xm3=Xm[(t+3)*XSTR+c];
            float a=bias + wv.x*xm0 + wv.y*xm1 + wv.z*xm2 + wv.w*xm3;
            xcr[t]=a/(1.f+__expf(-a));
            xm0=xm1; xm1=xm2; xm2=xm3;
        }
        __syncthreads();
        #pragma unroll
        for(int t=0;t<32;t++){
            Xm[(t+3)*XSTR+c]=xcr[t];
            xcg[((size_t)(tok0+t))*256+c]=xcr[t];
        }
    }
    __syncthreads();
    int tok=tid>>3, ng=tid&7;
    float acc[5]={0.f,0.f,0.f,0.f,0.f};
    const float* xr = Xm + (tok+3)*XSTR;
    for(int k=0;k<256;k+=4){
        float4 xv=*(const float4*)(xr+k);
        #pragma unroll
        for(int j=0;j<5;j++){
            float4 wv=*(const float4*)(Ws+(ng+8*j)*XSTR+k);
            acc[j]=fmaf(xv.x,wv.x,acc[j]); acc[j]=fmaf(xv.y,wv.y,acc[j]);
            acc[j]=fmaf(xv.z,wv.z,acc[j]); acc[j]=fmaf(xv.w,wv.w,acc[j]);
        }
    }
    #pragma unroll
    for(int j=0;j<5;j++) dbc[((size_t)(tok0+tok))*40 + ng+8*j] = acc[j];
    dtl[tok*8+ng]=acc[0];
    __syncthreads();
    float dl[8];
    #pragma unroll
    for(int q=0;q<8;q++) dl[q]=dtl[tok*8+q];
    int dbase=(tid&7)*32;
    float* dto = dtout + (size_t)(tok0+tok)*256;
    for(int jj=0;jj<32;jj++){
        int d=dbase+jj;
        float a=dpb[d];
        const float* wr=&dpws[d*8];
        #pragma unroll
        for(int q=0;q<8;q++) a += dl[q]*wr[q];
        dto[d] = (a>20.f)? a : log1pf(__expf(a));
    }
}

__global__ __launch_bounds__(128,4) void k_scan1(const float* __restrict__ dt,
        const float* __restrict__ xc, const float* __restrict__ dbc,
        const float* __restrict__ A_log, float* __restrict__ cP, float* __restrict__ cE){
    int bx=blockIdx.x;
    int half=bx&1, chunk=(bx>>1)&(NC-1), b=bx>>(1+6);
    int d=half*128+threadIdx.x;
    float Av[16]; bool ok=true;
    #pragma unroll
    for(int s=0;s<16;s++){
        float av=-__expf(A_log[d*16+s]); Av[s]=av;
        ok = ok && (fabsf(av+(float)(s+1))<1e-4f);
    }
    float h[16],P[16];
    #pragma unroll
    for(int s=0;s<16;s++){ h[s]=0.f; P[s]=1.f; }
    int row0=b*LQ+chunk*CLEN;
    const float* dtp=dt+(size_t)row0*256+d;
    const float* xcp=xc+(size_t)row0*256+d;
    #pragma unroll 2
    for(int t=0;t<CLEN;t++){
        float dtv=dtp[t*256], xcv=xcp[t*256];
        const float* br=dbc+(size_t)(row0+t)*40+8;
        float4 q0=*(const float4*)br, q1=*(const float4*)(br+4);
        float4 q2=*(const float4*)(br+8), q3=*(const float4*)(br+12);
        float bc[16]={q0.x,q0.y,q0.z,q0.w,q1.x,q1.y,q1.z,q1.w,
                      q2.x,q2.y,q2.z,q2.w,q3.x,q3.y,q3.z,q3.w};
        float a[16];
        if(ok){
            float e1=__expf(-dtv);
            a[0]=e1;
            #pragma unroll
            for(int s=1;s<16;s++) a[s]=a[s-1]*e1;
        }else{
            #pragma unroll
            for(int s=0;s<16;s++) a[s]=__expf(dtv*Av[s]);
        }
        float dx=dtv*xcv;
        #pragma unroll
        for(int s=0;s<16;s++){ h[s]=fmaf(a[s],h[s],dx*bc[s]); P[s]*=a[s]; }
    }
    size_t ci=((size_t)(b*256+d)*NC+chunk)*16;
    #pragma unroll
    for(int s=0;s<16;s+=4){
        *(float4*)&cP[ci+s]=make_float4(P[s],P[s+1],P[s+2],P[s+3]);
        *(float4*)&cE[ci+s]=make_float4(h[s],h[s+1],h[s+2],h[s+3]);
    }
}

__global__ void k_scan2(const float* __restrict__ P, const float* __restrict__ E,
                        float* __restrict__ Hi){
    int gid=blockIdx.x*256+threadIdx.x;
    int s=gid&15, bd=gid>>4;
    size_t base=(size_t)bd*NC*16+s;
    float h=0.f;
    #pragma unroll 8
    for(int c=0;c<NC;c++){
        Hi[base+c*16]=h;
        h = P[base+c*16]*h + E[base+c*16];
    }
}

__global__ __launch_bounds__(128,4) void k_scan3(const float* __restrict__ dt,
        const float* __restrict__ xc, const float* __restrict__ dbc,
        const float* __restrict__ A_log, const float* __restrict__ Hi,
        const float* __restrict__ xz, const float* __restrict__ D_,
        float* __restrict__ y){
    int bx=blockIdx.x;
    int half=bx&1, chunk=(bx>>1)&(NC-1), b=bx>>(1+6);
    int d=half*128+threadIdx.x;
    float Av[16]; bool ok=true;
    #pragma unroll
    for(int s=0;s<16;s++){
        float av=-__expf(A_log[d*16+s]); Av[s]=av;
        ok = ok && (fabsf(av+(float)(s+1))<1e-4f);
    }
    float Dv=D_[d];
    float h[16];
    size_t ci=((size_t)(b*256+d)*NC+chunk)*16;
    #pragma unroll
    for(int s=0;s<16;s+=4){
        float4 q=*(const float4*)&Hi[ci+s];
        h[s]=q.x; h[s+1]=q.y; h[s+2]=q.z; h[s+3]=q.w;
    }
    int row0=b*LQ+chunk*CLEN;
    const float* dtp=dt+(size_t)row0*256+d;
    const float* xcp=xc+(size_t)row0*256+d;
    const float* zp =xz+(size_t)row0*512+256+d;
    float* yp=y+(size_t)row0*256+d;
    #pragma unroll 2
    for(int t=0;t<CLEN;t++){
        float dtv=dtp[t*256], xcv=xcp[t*256];
        const float* br=dbc+(size_t)(row0+t)*40+8;
        float4 q0=*(const float4*)br, q1=*(const float4*)(br+4);
        float4 q2=*(const float4*)(br+8), q3=*(const float4*)(br+12);
        float4 c0=*(const float4*)(br+16), c1=*(const float4*)(br+20);
        float4 c2=*(const float4*)(br+24), c3=*(const float4*)(br+28);
        float bc[16]={q0.x,q0.y,q0.z,q0.w,q1.x,q1.y,q1.z,q1.w,
                      q2.x,q2.y,q2.z,q2.w,q3.x,q3.y,q3.z,q3.w};
        float cc[16]={c0.x,c0.y,c0.z,c0.w,c1.x,c1.y,c1.z,c1.w,
                      c2.x,c2.y,c2.z,c2.w,c3.x,c3.y,c3.z,c3.w};
        float a[16];
        if(ok){
            float e1=__expf(-dtv);
            a[0]=e1;
            #pragma unroll
            for(int s=1;s<16;s++) a[s]=a[s-1]*e1;
        }else{
            #pragma unroll
            for(int s=0;s<16;s++) a[s]=__expf(dtv*Av[s]);
        }
        float dx=dtv*xcv;
        float accy=0.f;
        #pragma unroll
        for(int s=0;s<16;s++){
            h[s]=fmaf(a[s],h[s],dx*bc[s]);
            accy=fmaf(h[s],cc[s],accy);
        }
        yp[t*256] = (accy + Dv*xcv) * zp[t*512];
    }
}

extern "C" void kernel_launch(void* const* d_in, const int* in_sizes, int n_in,
                              void* d_out, int out_size){
    const float* x        =(const float*)d_in[0];
    const float* pe       =(const float*)d_in[1];
    const float* norm_g   =(const float*)d_in[2];
    const float* norm_b   =(const float*)d_in[3];
    const float* conv1_w  =(const float*)d_in[4];
    const float* conv1_b  =(const float*)d_in[5];
    const float* ca1_w    =(const float*)d_in[6];
    const float* ca2_w    =(const float*)d_in[7];
    const float* conv2_w  =(const float*)d_in[8];
    const float* conv2_b  =(const float*)d_in[9];
    const float* head_w   =(const float*)d_in[10];
    const float* head_b   =(const float*)d_in[11];
    const float* in_proj_w=(const float*)d_in[12];
    const float* conv1d_w =(const float*)d_in[13];
    const float* conv1d_b =(const float*)d_in[14];
    const float* x_proj_w =(const float*)d_in[15];
    const float* dt_proj_w=(const float*)d_in[16];
    const float* dt_proj_b=(const float*)d_in[17];
    const float* A_log    =(const float*)d_in[18];
    const float* D_       =(const float*)d_in[19];
    const float* out_proj_w=(const float*)d_in[20];
    float* out=(float*)d_out;

    static bool attr_done=false;
    if(!attr_done){
        cudaFuncSetAttribute(k_xproj, cudaFuncAttributeMaxDynamicSharedMemorySize, 90000);
        attr_done=true;
    }

    float *feat,*pv,*casum,*ca,*sacc,*xT,*x1n,*xz,*xc,*dbc,*dt;
    float *cP,*cE,*Hi,*y; int* order;
    cudaGetSymbolAddress((void**)&feat, g_feat);
    cudaGetSymbolAddress((void**)&pv, g_pvterm);
    cudaGetSymbolAddress((void**)&casum, g_casum);
    cudaGetSymbolAddress((void**)&ca, g_ca);
    cudaGetSymbolAddress((void**)&sacc, g_scores);
    cudaGetSymbolAddress((void**)&order, g_order);
    cudaGetSymbolAddress((void**)&xT, g_xT);
    cudaGetSymbolAddress((void**)&x1n, g_x1n);
    cudaGetSymbolAddress((void**)&xz, g_xz);
    cudaGetSymbolAddress((void**)&xc, g_xc);
    cudaGetSymbolAddress((void**)&dbc, g_dbc);
    cudaGetSymbolAddress((void**)&dt, g_dt);
    cudaGetSymbolAddress((void**)&cP, g_cP);
    cudaGetSymbolAddress((void**)&cE, g_cE);
    cudaGetSymbolAddress((void**)&Hi, g_hinit);
    cudaGetSymbolAddress((void**)&y, g_y);

    k_pv<<<128,256>>>(x, pv, sacc);
    k_conv1<<<512,256>>>(x, conv1_w, conv1_b, feat, casum);
    k_ca<<<1,128>>>(casum, ca1_w, ca2_w, ca);
    k_score2<<<512,256>>>(feat, ca, conv2_w, conv2_b, head_w, sacc);
    k_sort<<<4,256>>>(sacc, pv, head_b, order);
    dim3 tb(32,8);
    k_transpose<<<dim3(128,4,4),tb>>>(x, xT);
    k_gather_ln<<<2048,256>>>(xT, pe, order, norm_g, norm_b, x1n);
    gemm_tf32<<<dim3(4,128),256>>>(x1n, in_proj_w, xz, 16384, 512, 128, 256, 0, 0);
    k_xproj<<<512,256,88000>>>(xz, conv1d_w, conv1d_b, x_proj_w, dt_proj_w,
                               dt_proj_b, xc, dbc, dt);
    k_scan1<<<512,128>>>(dt, xc, dbc, A_log, cP, cE);
    k_scan2<<<64,256>>>(cP, cE, Hi);
    k_scan3<<<512,128>>>(dt, xc, dbc, A_log, Hi, xz, D_, y);
    gemm_tf32<<<dim3(1,128),256>>>(y, out_proj_w, out, 16384, 128, 256, 1<<30,
                                   order, 1);
}

// round 14
// speedup vs baseline: 1.4595x; 1.4595x over previous
#include <cuda_runtime.h>
#include <math.h>
#include <stdint.h>

#define LQ 4096
#define NC 64
#define CLEN 64

__device__ float g_feat[4*128*4096];
__device__ float g_pvterm[4*4096];
__device__ float g_casum[4*128];
__device__ float g_ca[4*128];
__device__ float g_scores[4*4096];
__device__ int   g_order[4*4096];
__device__ float g_xT[4*4096*128];
__device__ float g_x1n[4*4096*128];
__device__ float g_xz[4*4096*512];
__device__ float g_xc[4*4096*256];
__device__ float g_dbc[4*4096*40];
__device__ float g_dt[4*4096*256];
__device__ float g_cP[4*256*NC*16];
__device__ float g_cE[4*256*NC*16];
__device__ float g_hinit[4*256*NC*16];
__device__ float g_y[4*4096*256];

__device__ __forceinline__ float sigmf(float x){ return 1.f/(1.f+__expf(-x)); }
__device__ __forceinline__ float geluf(float x){ return 0.5f*x*(1.f+erff(x*0.70710678f)); }
__device__ __forceinline__ float warp_sum(float v){
    v += __shfl_xor_sync(~0u,v,16); v += __shfl_xor_sync(~0u,v,8);
    v += __shfl_xor_sync(~0u,v,4);  v += __shfl_xor_sync(~0u,v,2);
    v += __shfl_xor_sync(~0u,v,1);  return v;
}
__device__ __forceinline__ uint32_t f2tf(float f){
    uint32_t r; asm("cvt.rna.tf32.f32 %0, %1;" : "=r"(r) : "f"(f)); return r;
}

__global__ void k_pv(const float* __restrict__ x, float* __restrict__ pv,
                     float* __restrict__ sacc){
    int p = blockIdx.x*256+threadIdx.x;
    int b = p>>12, hw = p&4095;
    const float* xp = x + (size_t)b*128*LQ + hw;
    float s=0.f,s2=0.f;
    #pragma unroll 8
    for(int c=0;c<128;c++){ float v=xp[c*LQ]; s+=v; s2+=v*v; }
    float var = (s2 - s*s*(1.f/128.f))*(1.f/127.f);
    pv[p] = 0.3f*sigmf(10.f*var);
    sacc[p] = 0.f;
}

__global__ __launch_bounds__(256) void k_conv1(const float* __restrict__ x,
        const float* __restrict__ w_, const float* __restrict__ b_,
        float* __restrict__ feat, float* __restrict__ casum){
    __shared__ float pl[66*66]; __shared__ float rs[8];
    int bc = blockIdx.x, c = bc&127, tid = threadIdx.x;
    const float* xp = x + (size_t)bc*4096;
    for(int i=tid;i<4356;i+=256) pl[i]=0.f;
    __syncthreads();
    for(int i=tid;i<4096;i+=256){ int h=i>>6,w=i&63; pl[(h+1)*66+w+1]=xp[i]; }
    float w[9];
    #pragma unroll
    for(int q=0;q<9;q++) w[q]=w_[c*9+q];
    float bias=b_[c];
    __syncthreads();
    float lsum=0.f;
    #pragma unroll 4
    for(int i=0;i<16;i++){
        int p=tid+i*256, h=p>>6, ww=p&63;
        const float* bp=&pl[h*66+ww];
        float s=bias
          + w[0]*bp[0]  + w[1]*bp[1]  + w[2]*bp[2]
          + w[3]*bp[66] + w[4]*bp[67] + w[5]*bp[68]
          + w[6]*bp[132]+ w[7]*bp[133]+ w[8]*bp[134];
        float g=geluf(s);
        feat[(size_t)bc*4096+p]=g; lsum+=g;
    }
    lsum=warp_sum(lsum);
    if((tid&31)==0) rs[tid>>5]=lsum;
    __syncthreads();
    if(tid==0){ float t=0.f; for(int q=0;q<8;q++) t+=rs[q]; casum[bc]=t; }
}

__global__ void k_ca(const float* __restrict__ casum, const float* __restrict__ w1,
                     const float* __restrict__ w2, float* __restrict__ ca){
    __shared__ float mean[4][128]; __shared__ float hid[4][32];
    int tid=threadIdx.x;
    for(int i=0;i<4;i++) mean[i][tid]=casum[i*128+tid]*(1.f/4096.f);
    __syncthreads();
    int b=tid>>5, j=tid&31;
    float h=0.f;
    for(int c=0;c<128;c++) h += mean[b][c]*w1[j*128+c];
    hid[b][j]=fmaxf(h,0.f);
    __syncthreads();
    for(int b2=0;b2<4;b2++){
        float v=0.f;
        #pragma unroll
        for(int j2=0;j2<32;j2++) v += hid[b2][j2]*w2[tid*32+j2];
        ca[b2*128+tid]=sigmf(v);
    }
}

__global__ __launch_bounds__(256) void k_score2(const float* __restrict__ feat,
        const float* __restrict__ ca, const float* __restrict__ w2_,
        const float* __restrict__ b2_, const float* __restrict__ hw_,
        float* __restrict__ sacc){
    __shared__ float pl[66*66];
    int bc=blockIdx.x, b=bc>>7, c=bc&127, tid=threadIdx.x;
    const float* fp=feat+(size_t)bc*4096;
    for(int i=tid;i<4356;i+=256) pl[i]=0.f;
    __syncthreads();
    for(int i=tid;i<4096;i+=256){ int h=i>>6,w=i&63; pl[(h+1)*66+w+1]=fp[i]; }
    float w[9];
    #pragma unroll
    for(int q=0;q<9;q++) w[q]=w2_[c*9+q];
    float cav=ca[bc], bias=b2_[c], hwc=hw_[c];
    __syncthreads();
    #pragma unroll 4
    for(int i=0;i<16;i++){
        int p=tid+i*256, h=p>>6, ww=p&63;
        const float* bp=&pl[h*66+ww];
        float s=
            w[0]*bp[0]  + w[1]*bp[1]  + w[2]*bp[2]
          + w[3]*bp[66] + w[4]*bp[67] + w[5]*bp[68]
          + w[6]*bp[132]+ w[7]*bp[133]+ w[8]*bp[134];
        float v = cav*s + bias;
        atomicAdd(&sacc[b*4096+p], geluf(v)*hwc);
    }
}

__global__ void k_sort(const float* __restrict__ sacc, const float* __restrict__ pv,
                       const float* __restrict__ hb_, int* __restrict__ order){
    __shared__ float sm[256];
    int b=blockIdx.x, p=threadIdx.x, py=p>>4, px=p&15;
    float hb0=hb_[0];
    float s=0.f;
    #pragma unroll
    for(int r=0;r<4;r++)
        #pragma unroll
        for(int cx=0;cx<4;cx++){
            int pix=(py*4+r)*64+px*4+cx;
            s += 0.7f*sigmf(sacc[b*4096+pix]+hb0) + pv[b*4096+pix];
        }
    sm[p]=s;
    __syncthreads();
    float mys=sm[p]; int rank=0;
    for(int j=0;j<256;j++){ float o=sm[j]; rank += (o>mys)||(o==mys && j<p); }
    #pragma unroll
    for(int j=0;j<16;j++){
        int pix=(py*4+(j>>2))*64 + px*4 + (j&3);
        order[b*4096+rank*16+j]=pix;
    }
}

__global__ void k_transpose(const float* __restrict__ x, float* __restrict__ xT){
    __shared__ float tile[32][33];
    int b=blockIdx.z, c0=blockIdx.y*32, p0=blockIdx.x*32;
    int tx=threadIdx.x, ty=threadIdx.y;
    for(int i=0;i<32;i+=8)
        tile[ty+i][tx] = x[((size_t)(b*128+c0+ty+i))*4096 + p0+tx];
    __syncthreads();
    for(int i=0;i<32;i+=8)
        xT[((size_t)(b*4096+p0+ty+i))*128 + c0+tx] = tile[tx][ty+i];
}

__global__ __launch_bounds__(256) void k_gather_ln(const float* __restrict__ xT,
        const float* __restrict__ pe, const int* __restrict__ order,
        const float* __restrict__ g_, const float* __restrict__ bn_,
        float* __restrict__ out){
    int warp=threadIdx.x>>5, lane=threadIdx.x&31;
    int token=blockIdx.x*8+warp, b=token>>12;
    int pix=order[token];
    float4 v=*(const float4*)&xT[((size_t)(b*4096+pix))*128+lane*4];
    float4 p=*(const float4*)&pe[pix*128+lane*4];
    v.x+=p.x; v.y+=p.y; v.z+=p.z; v.w+=p.w;
    float s=v.x+v.y+v.z+v.w;
    float s2=v.x*v.x+v.y*v.y+v.z*v.z+v.w*v.w;
    s=warp_sum(s); s2=warp_sum(s2);
    float mu=s*(1.f/128.f);
    float rstd=rsqrtf(s2*(1.f/128.f)-mu*mu+1e-5f);
    float4 g4=*(const float4*)&g_[lane*4];
    float4 b4=*(const float4*)&bn_[lane*4];
    float4 o;
    o.x=(v.x-mu)*rstd*g4.x+b4.x; o.y=(v.y-mu)*rstd*g4.y+b4.y;
    o.z=(v.z-mu)*rstd*g4.z+b4.z; o.w=(v.w-mu)*rstd*g4.w+b4.w;
    *(float4*)&out[(size_t)token*128+lane*4]=o;
}

#define GSTR 140
__global__ __launch_bounds__(256) void gemm_tf32(const float* __restrict__ A,
        const float* __restrict__ Bw, float* __restrict__ C, int M,int N,int K,
        int silu_from, const int* __restrict__ ord, int do_scatter){
    __shared__ uint32_t As[2][16][GSTR];
    __shared__ uint32_t Bs[2][16][GSTR];
    const int bm=blockIdx.y*128, bn=blockIdx.x*128;
    const int tid=threadIdx.x, lane=tid&31, warp=tid>>5;
    const int wm=(warp&1)*64, wn=(warp>>1)*32;
    const int g=lane>>2, tg=lane&3;
    const int lr=tid>>2, lq=(tid&3)*4;
    float acc[4][4][4];
    #pragma unroll
    for(int i=0;i<4;i++)
        #pragma unroll
        for(int j=0;j<4;j++)
            #pragma unroll
            for(int q=0;q<4;q++) acc[i][j][q]=0.f;
    const float* Ag = A + (size_t)(bm+lr)*K + lq;
    const float* Bg = Bw + (size_t)(bn+lr)*K + lq;
    const size_t sk64 = (size_t)64*K;
    float4 ra0,ra1,rb0,rb1;
    ra0=*(const float4*)(Ag); ra1=*(const float4*)(Ag+sk64);
    rb0=*(const float4*)(Bg); rb1=*(const float4*)(Bg+sk64);
    {
        As[0][lq+0][lr]=f2tf(ra0.x); As[0][lq+1][lr]=f2tf(ra0.y);
        As[0][lq+2][lr]=f2tf(ra0.z); As[0][lq+3][lr]=f2tf(ra0.w);
        As[0][lq+0][lr+64]=f2tf(ra1.x); As[0][lq+1][lr+64]=f2tf(ra1.y);
        As[0][lq+2][lr+64]=f2tf(ra1.z); As[0][lq+3][lr+64]=f2tf(ra1.w);
        Bs[0][lq+0][lr]=f2tf(rb0.x); Bs[0][lq+1][lr]=f2tf(rb0.y);
        Bs[0][lq+2][lr]=f2tf(rb0.z); Bs[0][lq+3][lr]=f2tf(rb0.w);
        Bs[0][lq+0][lr+64]=f2tf(rb1.x); Bs[0][lq+1][lr+64]=f2tf(rb1.y);
        Bs[0][lq+2][lr+64]=f2tf(rb1.z); Bs[0][lq+3][lr+64]=f2tf(rb1.w);
    }
    __syncthreads();
    const int nk=K>>4;
    for(int kt=0;kt<nk;kt++){
        const int cur=kt&1;
        if(kt+1<nk){
            ra0=*(const float4*)(Ag+(kt+1)*16);
            ra1=*(const float4*)(Ag+sk64+(kt+1)*16);
            rb0=*(const float4*)(Bg+(kt+1)*16);
            rb1=*(const float4*)(Bg+sk64+(kt+1)*16);
        }
        #pragma unroll
        for(int ks=0;ks<2;ks++){
            uint32_t af[4][4], bf[4][2];
            #pragma unroll
            for(int i=0;i<4;i++){
                int row=wm+16*i+g;
                af[i][0]=As[cur][ks*8+tg][row];
                af[i][1]=As[cur][ks*8+tg][row+8];
                af[i][2]=As[cur][ks*8+tg+4][row];
                af[i][3]=As[cur][ks*8+tg+4][row+8];
            }
            #pragma unroll
            for(int j=0;j<4;j++){
                int col=wn+8*j+g;
                bf[j][0]=Bs[cur][ks*8+tg][col];
                bf[j][1]=Bs[cur][ks*8+tg+4][col];
            }
            #pragma unroll
            for(int i=0;i<4;i++)
                #pragma unroll
                for(int j=0;j<4;j++){
                    asm volatile(
                      "mma.sync.aligned.m16n8k8.row.col.f32.tf32.tf32.f32 "
                      "{%0,%1,%2,%3},{%4,%5,%6,%7},{%8,%9},{%0,%1,%2,%3};"
                      : "+f"(acc[i][j][0]),"+f"(acc[i][j][1]),
                        "+f"(acc[i][j][2]),"+f"(acc[i][j][3])
                      : "r"(af[i][0]),"r"(af[i][1]),"r"(af[i][2]),"r"(af[i][3]),
                        "r"(bf[j][0]),"r"(bf[j][1]));
                }
        }
        if(kt+1<nk){
            const int nb=(kt+1)&1;
            As[nb][lq+0][lr]=f2tf(ra0.x); As[nb][lq+1][lr]=f2tf(ra0.y);
            As[nb][lq+2][lr]=f2tf(ra0.z); As[nb][lq+3][lr]=f2tf(ra0.w);
            As[nb][lq+0][lr+64]=f2tf(ra1.x); As[nb][lq+1][lr+64]=f2tf(ra1.y);
            As[nb][lq+2][lr+64]=f2tf(ra1.z); As[nb][lq+3][lr+64]=f2tf(ra1.w);
            Bs[nb][lq+0][lr]=f2tf(rb0.x); Bs[nb][lq+1][lr]=f2tf(rb0.y);
            Bs[nb][lq+2][lr]=f2tf(rb0.z); Bs[nb][lq+3][lr]=f2tf(rb0.w);
            Bs[nb][lq+0][lr+64]=f2tf(rb1.x); Bs[nb][lq+1][lr+64]=f2tf(rb1.y);
            Bs[nb][lq+2][lr+64]=f2tf(rb1.z); Bs[nb][lq+3][lr+64]=f2tf(rb1.w);
        }
        __syncthreads();
    }
    if(do_scatter){
        #pragma unroll
        for(int i=0;i<4;i++){
            int row=bm+wm+16*i+g;
            int b=row>>12;
            int p1=ord[row], p2=ord[row+8];
            #pragma unroll
            for(int j=0;j<4;j++){
                int col=bn+wn+8*j+2*tg;
                float* o1=C+((size_t)(b*128+col))*4096;
                float* o2=C+((size_t)(b*128+col+1))*4096;
                o1[p1]=acc[i][j][0]; o2[p1]=acc[i][j][1];
                o1[p2]=acc[i][j][2]; o2[p2]=acc[i][j][3];
            }
        }
    }else{
        #pragma unroll
        for(int i=0;i<4;i++)
            #pragma unroll
            for(int j=0;j<4;j++){
                int row=bm+wm+16*i+g, col=bn+wn+8*j+2*tg;
                float4 o=make_float4(acc[i][j][0],acc[i][j][1],acc[i][j][2],acc[i][j][3]);
                if(col>=silu_from){
                    o.x*=sigmf(o.x); o.y*=sigmf(o.y);
                    o.z*=sigmf(o.z); o.w*=sigmf(o.w);
                }
                float* cp=C+(size_t)row*N+col;
                *(float2*)cp = make_float2(o.x,o.y);
                *(float2*)(cp+(size_t)8*N) = make_float2(o.z,o.w);
            }
    }
}

#define XSTR 260
extern __shared__ float smemx[];
__global__ __launch_bounds__(256) void k_xproj(const float* __restrict__ xz,
        const float* __restrict__ cw, const float* __restrict__ cb,
        const float* __restrict__ xpw, const float* __restrict__ dpw,
        const float* __restrict__ dpb, float* __restrict__ xcg,
        float* __restrict__ dbc, float* __restrict__ dtout){
    float* Ws = smemx;
    float* Xm = smemx + 40*XSTR;
    float* dpws = smemx + 75*XSTR;
    float* dtl  = dpws + 2048;
    int tid=threadIdx.x, tok0=blockIdx.x*32;
    int l0=tok0&4095;
    for(int i=tid;i<2560;i+=256){
        int r=i>>6, c4=(i&63)<<2;
        float4 v=*(const float4*)&xpw[r*256+c4];
        float* dst=&Ws[r*XSTR+c4];
        dst[0]=v.x; dst[1]=v.y; dst[2]=v.z; dst[3]=v.w;
    }
    for(int i=tid;i<2240;i+=256){
        int r=i>>6, c4=(i&63)<<2;
        float4 v=make_float4(0.f,0.f,0.f,0.f);
        if(l0+r>=3) v=*(const float4*)&xz[((size_t)(tok0-3+r))*512+c4];
        float* dst=&Xm[r*XSTR+c4];
        dst[0]=v.x; dst[1]=v.y; dst[2]=v.z; dst[3]=v.w;
    }
    for(int i=tid;i<2048;i+=256) dpws[i]=dpw[i];
    __syncthreads();
    {
        int c=tid;
        float4 wv=*(const float4*)&cw[c*4];
        float bias=cb[c];
        float xm0=Xm[0*XSTR+c], xm1=Xm[1*XSTR+c], xm2=Xm[2*XSTR+c];
        float xcr[32];
        #pragma unroll
        for(int t=0;t<32;t++){
            float xm3=Xm[(t+3)*XSTR+c];
            float a=bias + wv.x*xm0 + wv.y*xm1 + wv.z*xm2 + wv.w*xm3;
            xcr[t]=a/(1.f+__expf(-a));
            xm0=xm1; xm1=xm2; xm2=xm3;
        }
        __syncthreads();
        #pragma unroll
        for(int t=0;t<32;t++){
            Xm[(t+3)*XSTR+c]=xcr[t];
            xcg[((size_t)(tok0+t))*256+c]=xcr[t];
        }
    }
    __syncthreads();
    int tok=tid>>3, ng=tid&7;
    float acc[5]={0.f,0.f,0.f,0.f,0.f};
    const float* xr = Xm + (tok+3)*XSTR;
    for(int k=0;k<256;k+=4){
        float4 xv=*(const float4*)(xr+k);
        #pragma unroll
        for(int j=0;j<5;j++){
            float4 wv=*(const float4*)(Ws+(ng+8*j)*XSTR+k);
            acc[j]=fmaf(xv.x,wv.x,acc[j]); acc[j]=fmaf(xv.y,wv.y,acc[j]);
            acc[j]=fmaf(xv.z,wv.z,acc[j]); acc[j]=fmaf(xv.w,wv.w,acc[j]);
        }
    }
    #pragma unroll
    for(int j=0;j<5;j++) dbc[((size_t)(tok0+tok))*40 + ng+8*j] = acc[j];
    dtl[tok*8+ng]=acc[0];
    __syncthreads();
    float dl[8];
    #pragma unroll
    for(int q=0;q<8;q++) dl[q]=dtl[tok*8+q];
    int dbase=(tid&7)*32;
    float* dto = dtout + (size_t)(tok0+tok)*256;
    for(int jj=0;jj<32;jj++){
        int d=dbase+jj;
        float a=dpb[d];
        const float* wr=&dpws[d*8];
        #pragma unroll
        for(int q=0;q<8;q++) a += dl[q]*wr[q];
        dto[d] = (a>20.f)? a : log1pf(__expf(a));
    }
}

__global__ __launch_bounds__(128,4) void k_scan1(const float* __restrict__ dt,
        const float* __restrict__ xc, const float* __restrict__ dbc,
        const float* __restrict__ A_log, float* __restrict__ cP, float* __restrict__ cE){
    int bx=blockIdx.x;
    int half=bx&1, chunk=(bx>>1)&(NC-1), b=bx>>(1+6);
    int d=half*128+threadIdx.x;
    float Av[16]; bool ok=true;
    #pragma unroll
    for(int s=0;s<16;s++){
        float av=-__expf(A_log[d*16+s]); Av[s]=av;
        ok = ok && (fabsf(av+(float)(s+1))<1e-4f);
    }
    float h[16],P[16];
    #pragma unroll
    for(int s=0;s<16;s++){ h[s]=0.f; P[s]=1.f; }
    int row0=b*LQ+chunk*CLEN;
    const float* dtp=dt+(size_t)row0*256+d;
    const float* xcp=xc+(size_t)row0*256+d;
    #pragma unroll 2
    for(int t=0;t<CLEN;t++){
        float dtv=dtp[t*256], xcv=xcp[t*256];
        const float* br=dbc+(size_t)(row0+t)*40+8;
        float4 q0=*(const float4*)br, q1=*(const float4*)(br+4);
        float4 q2=*(const float4*)(br+8), q3=*(const float4*)(br+12);
        float bc[16]={q0.x,q0.y,q0.z,q0.w,q1.x,q1.y,q1.z,q1.w,
                      q2.x,q2.y,q2.z,q2.w,q3.x,q3.y,q3.z,q3.w};
        float a[16];
        if(ok){
            float e1=__expf(-dtv);
            a[0]=e1;
            #pragma unroll
            for(int s=1;s<16;s++) a[s]=a[s-1]*e1;
        }else{
            #pragma unroll
            for(int s=0;s<16;s++) a[s]=__expf(dtv*Av[s]);
        }
        float dx=dtv*xcv;
        #pragma unroll
        for(int s=0;s<16;s++){ h[s]=fmaf(a[s],h[s],dx*bc[s]); P[s]*=a[s]; }
    }
    size_t ci=((size_t)(b*256+d)*NC+chunk)*16;
    #pragma unroll
    for(int s=0;s<16;s+=4){
        *(float4*)&cP[ci+s]=make_float4(P[s],P[s+1],P[s+2],P[s+3]);
        *(float4*)&cE[ci+s]=make_float4(h[s],h[s+1],h[s+2],h[s+3]);
    }
}

__global__ void k_scan2(const float* __restrict__ P, const float* __restrict__ E,
                        float* __restrict__ Hi){
    int gid=blockIdx.x*256+threadIdx.x;
    int s=gid&15, bd=gid>>4;
    size_t base=(size_t)bd*NC*16+s;
    float h=0.f;
    #pragma unroll 8
    for(int c=0;c<NC;c++){
        Hi[base+c*16]=h;
        h = P[base+c*16]*h + E[base+c*16];
    }
}

__global__ __launch_bounds__(128,4) void k_scan3(const float* __restrict__ dt,
        const float* __restrict__ xc, const float* __restrict__ dbc,
        const float* __restrict__ A_log, const float* __restrict__ Hi,
        const float* __restrict__ xz, const float* __restrict__ D_,
        float* __restrict__ y){
    int bx=blockIdx.x;
    int half=bx&1, chunk=(bx>>1)&(NC-1), b=bx>>(1+6);
    int d=half*128+threadIdx.x;
    float Av[16]; bool ok=true;
    #pragma unroll
    for(int s=0;s<16;s++){
        float av=-__expf(A_log[d*16+s]); Av[s]=av;
        ok = ok && (fabsf(av+(float)(s+1))<1e-4f);
    }
    float Dv=D_[d];
    float h[16];
    size_t ci=((size_t)(b*256+d)*NC+chunk)*16;
    #pragma unroll
    for(int s=0;s<16;s+=4){
        float4 q=*(const float4*)&Hi[ci+s];
        h[s]=q.x; h[s+1]=q.y; h[s+2]=q.z; h[s+3]=q.w;
    }
    int row0=b*LQ+chunk*CLEN;
    const float* dtp=dt+(size_t)row0*256+d;
    const float* xcp=xc+(size_t)row0*256+d;
    const float* zp =xz+(size_t)row0*512+256+d;
    float* yp=y+(size_t)row0*256+d;
    #pragma unroll 2
    for(int t=0;t<CLEN;t++){
        float dtv=dtp[t*256], xcv=xcp[t*256];
        const float* br=dbc+(size_t)(row0+t)*40+8;
        float4 q0=*(const float4*)br, q1=*(const float4*)(br+4);
        float4 q2=*(const float4*)(br+8), q3=*(const float4*)(br+12);
        float4 c0=*(const float4*)(br+16), c1=*(const float4*)(br+20);
        float4 c2=*(const float4*)(br+24), c3=*(const float4*)(br+28);
        float bc[16]={q0.x,q0.y,q0.z,q0.w,q1.x,q1.y,q1.z,q1.w,
                      q2.x,q2.y,q2.z,q2.w,q3.x,q3.y,q3.z,q3.w};
        float cc[16]={c0.x,c0.y,c0.z,c0.w,c1.x,c1.y,c1.z,c1.w,
                      c2.x,c2.y,c2.z,c2.w,c3.x,c3.y,c3.z,c3.w};
        float a[16];
        if(ok){
            float e1=__expf(-dtv);
            a[0]=e1;
            #pragma unroll
            for(int s=1;s<16;s++) a[s]=a[s-1]*e1;
        }else{
            #pragma unroll
            for(int s=0;s<16;s++) a[s]=__expf(dtv*Av[s]);
        }
        float dx=dtv*xcv;
        float accy=0.f;
        #pragma unroll
        for(int s=0;s<16;s++){
            h[s]=fmaf(a[s],h[s],dx*bc[s]);
            accy=fmaf(h[s],cc[s],accy);
        }
        yp[t*256] = (accy + Dv*xcv) * zp[t*512];
    }
}

extern "C" void kernel_launch(void* const* d_in, const int* in_sizes, int n_in,
                              void* d_out, int out_size){
    const float* x        =(const float*)d_in[0];
    const float* pe       =(const float*)d_in[1];
    const float* norm_g   =(const float*)d_in[2];
    const float* norm_b   =(const float*)d_in[3];
    const float* conv1_w  =(const float*)d_in[4];
    const float* conv1_b  =(const float*)d_in[5];
    const float* ca1_w    =(const float*)d_in[6];
    const float* ca2_w    =(const float*)d_in[7];
    const float* conv2_w  =(const float*)d_in[8];
    const float* conv2_b  =(const float*)d_in[9];
    const float* head_w   =(const float*)d_in[10];
    const float* head_b   =(const float*)d_in[11];
    const float* in_proj_w=(const float*)d_in[12];
    const float* conv1d_w =(const float*)d_in[13];
    const float* conv1d_b =(const float*)d_in[14];
    const float* x_proj_w =(const float*)d_in[15];
    const float* dt_proj_w=(const float*)d_in[16];
    const float* dt_proj_b=(const float*)d_in[17];
    const float* A_log    =(const float*)d_in[18];
    const float* D_       =(const float*)d_in[19];
    const float* out_proj_w=(const float*)d_in[20];
    float* out=(float*)d_out;

    static bool attr_done=false;
    if(!attr_done){
        cudaFuncSetAttribute(k_xproj, cudaFuncAttributeMaxDynamicSharedMemorySize, 90000);
        attr_done=true;
    }

    float *feat,*pv,*casum,*ca,*sacc,*xT,*x1n,*xz,*xc,*dbc,*dt;
    float *cP,*cE,*Hi,*y; int* order;
    cudaGetSymbolAddress((void**)&feat, g_feat);
    cudaGetSymbolAddress((void**)&pv, g_pvterm);
    cudaGetSymbolAddress((void**)&casum, g_casum);
    cudaGetSymbolAddress((void**)&ca, g_ca);
    cudaGetSymbolAddress((void**)&sacc, g_scores);
    cudaGetSymbolAddress((void**)&order, g_order);
    cudaGetSymbolAddress((void**)&xT, g_xT);
    cudaGetSymbolAddress((void**)&x1n, g_x1n);
    cudaGetSymbolAddress((void**)&xz, g_xz);
    cudaGetSymbolAddress((void**)&xc, g_xc);
    cudaGetSymbolAddress((void**)&dbc, g_dbc);
    cudaGetSymbolAddress((void**)&dt, g_dt);
    cudaGetSymbolAddress((void**)&cP, g_cP);
    cudaGetSymbolAddress((void**)&cE, g_cE);
    cudaGetSymbolAddress((void**)&Hi, g_hinit);
    cudaGetSymbolAddress((void**)&y, g_y);

    k_pv<<<64,256>>>(x, pv, sacc);
    k_conv1<<<512,256>>>(x, conv1_w, conv1_b, feat, casum);
    k_ca<<<1,128>>>(casum, ca1_w, ca2_w, ca);
    k_score2<<<512,256>>>(feat, ca, conv2_w, conv2_b, head_w, sacc);
    k_sort<<<4,256>>>(sacc, pv, head_b, order);
    dim3 tb(32,8);
    k_transpose<<<dim3(128,4,4),tb>>>(x, xT);
    k_gather_ln<<<2048,256>>>(xT, pe, order, norm_g, norm_b, x1n);
    gemm_tf32<<<dim3(4,128),256>>>(x1n, in_proj_w, xz, 16384, 512, 128, 256, 0, 0);
    k_xproj<<<512,256,88000>>>(xz, conv1d_w, conv1d_b, x_proj_w, dt_proj_w,
                               dt_proj_b, xc, dbc, dt);
    k_scan1<<<512,128>>>(dt, xc, dbc, A_log, cP, cE);
    k_scan2<<<64,256>>>(cP, cE, Hi);
    k_scan3<<<512,128>>>(dt, xc, dbc, A_log, Hi, xz, D_, y);
    gemm_tf32<<<dim3(1,128),256>>>(y, out_proj_w, out, 16384, 128, 256, 1<<30,
                                   order, 1);
}

// round 15
// speedup vs baseline: 1.5015x; 1.0287x over previous
#include <cuda_runtime.h>
#include <math.h>
#include <stdint.h>

#define LQ 4096
#define NC 64
#define CLEN 64

__device__ float g_feat[4*128*4096];
__device__ float g_pvterm[4*4096];
__device__ float g_casum[4*128];
__device__ float g_ca[4*128];
__device__ float g_scores[4*4096];
__device__ int   g_order[4*4096];
__device__ float g_xT[4*4096*128];
__device__ float g_x1n[4*4096*128];
__device__ float g_xz[4*4096*512];
__device__ float g_xc[4*4096*256];
__device__ float g_dbc[4*4096*40];
__device__ float g_dt[4*4096*256];
__device__ float g_cP[4*256*NC*16];
__device__ float g_cE[4*256*NC*16];
__device__ float g_hinit[4*256*NC*16];
__device__ float g_y[4*4096*256];

__device__ __forceinline__ float sigmf(float x){ return 1.f/(1.f+__expf(-x)); }
__device__ __forceinline__ float geluf(float x){ return 0.5f*x*(1.f+erff(x*0.70710678f)); }
__device__ __forceinline__ float warp_sum(float v){
    v += __shfl_xor_sync(~0u,v,16); v += __shfl_xor_sync(~0u,v,8);
    v += __shfl_xor_sync(~0u,v,4);  v += __shfl_xor_sync(~0u,v,2);
    v += __shfl_xor_sync(~0u,v,1);  return v;
}
__device__ __forceinline__ uint32_t f2tf(float f){
    uint32_t r; asm("cvt.rna.tf32.f32 %0, %1;" : "=r"(r) : "f"(f)); return r;
}

__global__ void k_pv(const float* __restrict__ x, float* __restrict__ pv,
                     float* __restrict__ sacc){
    int p = blockIdx.x*256+threadIdx.x;
    int b = p>>12, hw = p&4095;
    const float* xp = x + (size_t)b*128*LQ + hw;
    float s=0.f,s2=0.f;
    #pragma unroll 8
    for(int c=0;c<128;c++){ float v=xp[c*LQ]; s+=v; s2+=v*v; }
    float var = (s2 - s*s*(1.f/128.f))*(1.f/127.f);
    pv[p] = 0.3f*sigmf(10.f*var);
    sacc[p] = 0.f;
}

// round-8 style: unpadded plane, float4 fill, predicated 9-tap
__global__ __launch_bounds__(256) void k_conv1(const float* __restrict__ x,
        const float* __restrict__ w_, const float* __restrict__ b_,
        float* __restrict__ feat, float* __restrict__ casum){
    __shared__ float pl[4096]; __shared__ float rs[8];
    int bc = blockIdx.x, c = bc&127, tid = threadIdx.x;
    const float* xp = x + (size_t)bc*4096;
    for(int i=tid;i<1024;i+=256) ((float4*)pl)[i] = ((const float4*)xp)[i];
    float w[9];
    #pragma unroll
    for(int q=0;q<9;q++) w[q]=w_[c*9+q];
    float bias=b_[c];
    __syncthreads();
    float lsum=0.f;
    #pragma unroll 4
    for(int i=0;i<16;i++){
        int p=tid+i*256, h=p>>6, ww=p&63;
        float s=bias;
        #pragma unroll
        for(int dy=-1;dy<=1;dy++){ int hh=h+dy; if((unsigned)hh<64u){
            #pragma unroll
            for(int dx=-1;dx<=1;dx++){ int wn=ww+dx; if((unsigned)wn<64u)
                s += w[(dy+1)*3+dx+1]*pl[hh*64+wn]; } } }
        float g=geluf(s);
        feat[(size_t)bc*4096+p]=g; lsum+=g;
    }
    lsum=warp_sum(lsum);
    if((tid&31)==0) rs[tid>>5]=lsum;
    __syncthreads();
    if(tid==0){ float t=0.f; for(int q=0;q<8;q++) t+=rs[q]; casum[bc]=t; }
}

__global__ void k_ca(const float* __restrict__ casum, const float* __restrict__ w1,
                     const float* __restrict__ w2, float* __restrict__ ca){
    __shared__ float mean[4][128]; __shared__ float hid[4][32];
    int tid=threadIdx.x;
    for(int i=0;i<4;i++) mean[i][tid]=casum[i*128+tid]*(1.f/4096.f);
    __syncthreads();
    int b=tid>>5, j=tid&31;
    float h=0.f;
    for(int c=0;c<128;c++) h += mean[b][c]*w1[j*128+c];
    hid[b][j]=fmaxf(h,0.f);
    __syncthreads();
    for(int b2=0;b2<4;b2++){
        float v=0.f;
        #pragma unroll
        for(int j2=0;j2<32;j2++) v += hid[b2][j2]*w2[tid*32+j2];
        ca[b2*128+tid]=sigmf(v);
    }
}

__global__ __launch_bounds__(256) void k_score2(const float* __restrict__ feat,
        const float* __restrict__ ca, const float* __restrict__ w2_,
        const float* __restrict__ b2_, const float* __restrict__ hw_,
        float* __restrict__ sacc){
    __shared__ float pl[4096];
    int bc=blockIdx.x, b=bc>>7, c=bc&127, tid=threadIdx.x;
    const float* fp=feat+(size_t)bc*4096;
    for(int i=tid;i<1024;i+=256) ((float4*)pl)[i]=((const float4*)fp)[i];
    float w[9];
    #pragma unroll
    for(int q=0;q<9;q++) w[q]=w2_[c*9+q];
    float cav=ca[bc], bias=b2_[c], hwc=hw_[c];
    __syncthreads();
    #pragma unroll 4
    for(int i=0;i<16;i++){
        int p=tid+i*256, h=p>>6, ww=p&63;
        float s=0.f;
        #pragma unroll
        for(int dy=-1;dy<=1;dy++){ int hh=h+dy; if((unsigned)hh<64u){
            #pragma unroll
            for(int dx=-1;dx<=1;dx++){ int wn=ww+dx; if((unsigned)wn<64u)
                s += w[(dy+1)*3+dx+1]*pl[hh*64+wn]; } } }
        float v = cav*s + bias;
        atomicAdd(&sacc[b*4096+p], geluf(v)*hwc);
    }
}

__global__ void k_sort(const float* __restrict__ sacc, const float* __restrict__ pv,
                       const float* __restrict__ hb_, int* __restrict__ order){
    __shared__ float sm[256];
    int b=blockIdx.x, p=threadIdx.x, py=p>>4, px=p&15;
    float hb0=hb_[0];
    float s=0.f;
    #pragma unroll
    for(int r=0;r<4;r++)
        #pragma unroll
        for(int cx=0;cx<4;cx++){
            int pix=(py*4+r)*64+px*4+cx;
            s += 0.7f*sigmf(sacc[b*4096+pix]+hb0) + pv[b*4096+pix];
        }
    sm[p]=s;
    __syncthreads();
    float mys=sm[p]; int rank=0;
    for(int j=0;j<256;j++){ float o=sm[j]; rank += (o>mys)||(o==mys && j<p); }
    #pragma unroll
    for(int j=0;j<16;j++){
        int pix=(py*4+(j>>2))*64 + px*4 + (j&3);
        order[b*4096+rank*16+j]=pix;
    }
}

__global__ void k_transpose(const float* __restrict__ x, float* __restrict__ xT){
    __shared__ float tile[32][33];
    int b=blockIdx.z, c0=blockIdx.y*32, p0=blockIdx.x*32;
    int tx=threadIdx.x, ty=threadIdx.y;
    for(int i=0;i<32;i+=8)
        tile[ty+i][tx] = x[((size_t)(b*128+c0+ty+i))*4096 + p0+tx];
    __syncthreads();
    for(int i=0;i<32;i+=8)
        xT[((size_t)(b*4096+p0+ty+i))*128 + c0+tx] = tile[tx][ty+i];
}

__global__ __launch_bounds__(256) void k_gather_ln(const float* __restrict__ xT,
        const float* __restrict__ pe, const int* __restrict__ order,
        const float* __restrict__ g_, const float* __restrict__ bn_,
        float* __restrict__ out){
    int warp=threadIdx.x>>5, lane=threadIdx.x&31;
    int token=blockIdx.x*8+warp, b=token>>12;
    int pix=order[token];
    float4 v=*(const float4*)&xT[((size_t)(b*4096+pix))*128+lane*4];
    float4 p=*(const float4*)&pe[pix*128+lane*4];
    v.x+=p.x; v.y+=p.y; v.z+=p.z; v.w+=p.w;
    float s=v.x+v.y+v.z+v.w;
    float s2=v.x*v.x+v.y*v.y+v.z*v.z+v.w*v.w;
    s=warp_sum(s); s2=warp_sum(s2);
    float mu=s*(1.f/128.f);
    float rstd=rsqrtf(s2*(1.f/128.f)-mu*mu+1e-5f);
    float4 g4=*(const float4*)&g_[lane*4];
    float4 b4=*(const float4*)&bn_[lane*4];
    float4 o;
    o.x=(v.x-mu)*rstd*g4.x+b4.x; o.y=(v.y-mu)*rstd*g4.y+b4.y;
    o.z=(v.z-mu)*rstd*g4.z+b4.z; o.w=(v.w-mu)*rstd*g4.w+b4.w;
    *(float4*)&out[(size_t)token*128+lane*4]=o;
}

#define GSTR 140
__global__ __launch_bounds__(256) void gemm_tf32(const float* __restrict__ A,
        const float* __restrict__ Bw, float* __restrict__ C, int M,int N,int K,
        int silu_from, const int* __restrict__ ord, int do_scatter){
    __shared__ uint32_t As[2][16][GSTR];
    __shared__ uint32_t Bs[2][16][GSTR];
    const int bm=blockIdx.y*128, bn=blockIdx.x*128;
    const int tid=threadIdx.x, lane=tid&31, warp=tid>>5;
    const int wm=(warp&1)*64, wn=(warp>>1)*32;
    const int g=lane>>2, tg=lane&3;
    const int lr=tid>>2, lq=(tid&3)*4;
    float acc[4][4][4];
    #pragma unroll
    for(int i=0;i<4;i++)
        #pragma unroll
        for(int j=0;j<4;j++)
            #pragma unroll
            for(int q=0;q<4;q++) acc[i][j][q]=0.f;
    const float* Ag = A + (size_t)(bm+lr)*K + lq;
    const float* Bg = Bw + (size_t)(bn+lr)*K + lq;
    const size_t sk64 = (size_t)64*K;
    float4 ra0,ra1,rb0,rb1;
    ra0=*(const float4*)(Ag); ra1=*(const float4*)(Ag+sk64);
    rb0=*(const float4*)(Bg); rb1=*(const float4*)(Bg+sk64);
    {
        As[0][lq+0][lr]=f2tf(ra0.x); As[0][lq+1][lr]=f2tf(ra0.y);
        As[0][lq+2][lr]=f2tf(ra0.z); As[0][lq+3][lr]=f2tf(ra0.w);
        As[0][lq+0][lr+64]=f2tf(ra1.x); As[0][lq+1][lr+64]=f2tf(ra1.y);
        As[0][lq+2][lr+64]=f2tf(ra1.z); As[0][lq+3][lr+64]=f2tf(ra1.w);
        Bs[0][lq+0][lr]=f2tf(rb0.x); Bs[0][lq+1][lr]=f2tf(rb0.y);
        Bs[0][lq+2][lr]=f2tf(rb0.z); Bs[0][lq+3][lr]=f2tf(rb0.w);
        Bs[0][lq+0][lr+64]=f2tf(rb1.x); Bs[0][lq+1][lr+64]=f2tf(rb1.y);
        Bs[0][lq+2][lr+64]=f2tf(rb1.z); Bs[0][lq+3][lr+64]=f2tf(rb1.w);
    }
    __syncthreads();
    const int nk=K>>4;
    for(int kt=0;kt<nk;kt++){
        const int cur=kt&1;
        if(kt+1<nk){
            ra0=*(const float4*)(Ag+(kt+1)*16);
            ra1=*(const float4*)(Ag+sk64+(kt+1)*16);
            rb0=*(const float4*)(Bg+(kt+1)*16);
            rb1=*(const float4*)(Bg+sk64+(kt+1)*16);
        }
        #pragma unroll
        for(int ks=0;ks<2;ks++){
            uint32_t af[4][4], bf[4][2];
            #pragma unroll
            for(int i=0;i<4;i++){
                int row=wm+16*i+g;
                af[i][0]=As[cur][ks*8+tg][row];
                af[i][1]=As[cur][ks*8+tg][row+8];
                af[i][2]=As[cur][ks*8+tg+4][row];
                af[i][3]=As[cur][ks*8+tg+4][row+8];
            }
            #pragma unroll
            for(int j=0;j<4;j++){
                int col=wn+8*j+g;
                bf[j][0]=Bs[cur][ks*8+tg][col];
                bf[j][1]=Bs[cur][ks*8+tg+4][col];
            }
            #pragma unroll
            for(int i=0;i<4;i++)
                #pragma unroll
                for(int j=0;j<4;j++){
                    asm volatile(
                      "mma.sync.aligned.m16n8k8.row.col.f32.tf32.tf32.f32 "
                      "{%0,%1,%2,%3},{%4,%5,%6,%7},{%8,%9},{%0,%1,%2,%3};"
                      : "+f"(acc[i][j][0]),"+f"(acc[i][j][1]),
                        "+f"(acc[i][j][2]),"+f"(acc[i][j][3])
                      : "r"(af[i][0]),"r"(af[i][1]),"r"(af[i][2]),"r"(af[i][3]),
                        "r"(bf[j][0]),"r"(bf[j][1]));
                }
        }
        if(kt+1<nk){
            const int nb=(kt+1)&1;
            As[nb][lq+0][lr]=f2tf(ra0.x); As[nb][lq+1][lr]=f2tf(ra0.y);
            As[nb][lq+2][lr]=f2tf(ra0.z); As[nb][lq+3][lr]=f2tf(ra0.w);
            As[nb][lq+0][lr+64]=f2tf(ra1.x); As[nb][lq+1][lr+64]=f2tf(ra1.y);
            As[nb][lq+2][lr+64]=f2tf(ra1.z); As[nb][lq+3][lr+64]=f2tf(ra1.w);
            Bs[nb][lq+0][lr]=f2tf(rb0.x); Bs[nb][lq+1][lr]=f2tf(rb0.y);
            Bs[nb][lq+2][lr]=f2tf(rb0.z); Bs[nb][lq+3][lr]=f2tf(rb0.w);
            Bs[nb][lq+0][lr+64]=f2tf(rb1.x); Bs[nb][lq+1][lr+64]=f2tf(rb1.y);
            Bs[nb][lq+2][lr+64]=f2tf(rb1.z); Bs[nb][lq+3][lr+64]=f2tf(rb1.w);
        }
        __syncthreads();
    }
    if(do_scatter){
        #pragma unroll
        for(int i=0;i<4;i++){
            int row=bm+wm+16*i+g;
            int b=row>>12;
            int p1=ord[row], p2=ord[row+8];
            #pragma unroll
            for(int j=0;j<4;j++){
                int col=bn+wn+8*j+2*tg;
                float* o1=C+((size_t)(b*128+col))*4096;
                float* o2=C+((size_t)(b*128+col+1))*4096;
                o1[p1]=acc[i][j][0]; o2[p1]=acc[i][j][1];
                o1[p2]=acc[i][j][2]; o2[p2]=acc[i][j][3];
            }
        }
    }else{
        #pragma unroll
        for(int i=0;i<4;i++)
            #pragma unroll
            for(int j=0;j<4;j++){
                int row=bm+wm+16*i+g, col=bn+wn+8*j+2*tg;
                float4 o=make_float4(acc[i][j][0],acc[i][j][1],acc[i][j][2],acc[i][j][3]);
                if(col>=silu_from){
                    o.x*=sigmf(o.x); o.y*=sigmf(o.y);
                    o.z*=sigmf(o.z); o.w*=sigmf(o.w);
                }
                float* cp=C+(size_t)row*N+col;
                *(float2*)cp = make_float2(o.x,o.y);
                *(float2*)(cp+(size_t)8*N) = make_float2(o.z,o.w);
            }
    }
}

#define XSTR 260
extern __shared__ float smemx[];
__global__ __launch_bounds__(256) void k_xproj(const float* __restrict__ xz,
        const float* __restrict__ cw, const float* __restrict__ cb,
        const float* __restrict__ xpw, const float* __restrict__ dpw,
        const float* __restrict__ dpb, float* __restrict__ xcg,
        float* __restrict__ dbc, float* __restrict__ dtout){
    float* Ws = smemx;
    float* Xm = smemx + 40*XSTR;
    float* dpws = smemx + 75*XSTR;
    float* dtl  = dpws + 2048;
    int tid=threadIdx.x, tok0=blockIdx.x*32;
    int l0=tok0&4095;
    for(int i=tid;i<2560;i+=256){
        int r=i>>6, c4=(i&63)<<2;
        float4 v=*(const float4*)&xpw[r*256+c4];
        float* dst=&Ws[r*XSTR+c4];
        dst[0]=v.x; dst[1]=v.y; dst[2]=v.z; dst[3]=v.w;
    }
    for(int i=tid;i<2240;i+=256){
        int r=i>>6, c4=(i&63)<<2;
        float4 v=make_float4(0.f,0.f,0.f,0.f);
        if(l0+r>=3) v=*(const float4*)&xz[((size_t)(tok0-3+r))*512+c4];
        float* dst=&Xm[r*XSTR+c4];
        dst[0]=v.x; dst[1]=v.y; dst[2]=v.z; dst[3]=v.w;
    }
    for(int i=tid;i<2048;i+=256) dpws[i]=dpw[i];
    __syncthreads();
    {
        int c=tid;
        float4 wv=*(const float4*)&cw[c*4];
        float bias=cb[c];
        float xm0=Xm[0*XSTR+c], xm1=Xm[1*XSTR+c], xm2=Xm[2*XSTR+c];
        float xcr[32];
        #pragma unroll
        for(int t=0;t<32;t++){
            float xm3=Xm[(t+3)*XSTR+c];
            float a=bias + wv.x*xm0 + wv.y*xm1 + wv.z*xm2 + wv.w*xm3;
            xcr[t]=a/(1.f+__expf(-a));
            xm0=xm1; xm1=xm2; xm2=xm3;
        }
        __syncthreads();
        #pragma unroll
        for(int t=0;t<32;t++){
            Xm[(t+3)*XSTR+c]=xcr[t];
            xcg[((size_t)(tok0+t))*256+c]=xcr[t];
        }
    }
    __syncthreads();
    int tok=tid>>3, ng=tid&7;
    float acc[5]={0.f,0.f,0.f,0.f,0.f};
    const float* xr = Xm + (tok+3)*XSTR;
    for(int k=0;k<256;k+=4){
        float4 xv=*(const float4*)(xr+k);
        #pragma unroll
        for(int j=0;j<5;j++){
            float4 wv=*(const float4*)(Ws+(ng+8*j)*XSTR+k);
            acc[j]=fmaf(xv.x,wv.x,acc[j]); acc[j]=fmaf(xv.y,wv.y,acc[j]);
            acc[j]=fmaf(xv.z,wv.z,acc[j]); acc[j]=fmaf(xv.w,wv.w,acc[j]);
        }
    }
    #pragma unroll
    for(int j=0;j<5;j++) dbc[((size_t)(tok0+tok))*40 + ng+8*j] = acc[j];
    dtl[tok*8+ng]=acc[0];
    __syncthreads();
    float dl[8];
    #pragma unroll
    for(int q=0;q<8;q++) dl[q]=dtl[tok*8+q];
    int dbase=(tid&7)*32;
    float* dto = dtout + (size_t)(tok0+tok)*256;
    for(int jj=0;jj<32;jj++){
        int d=dbase+jj;
        float a=dpb[d];
        const float* wr=&dpws[d*8];
        #pragma unroll
        for(int q=0;q<8;q++) a += dl[q]*wr[q];
        dto[d] = (a>20.f)? a : log1pf(__expf(a));
    }
}

__global__ __launch_bounds__(128,4) void k_scan1(const float* __restrict__ dt,
        const float* __restrict__ xc, const float* __restrict__ dbc,
        const float* __restrict__ A_log, float* __restrict__ cP, float* __restrict__ cE){
    int bx=blockIdx.x;
    int half=bx&1, chunk=(bx>>1)&(NC-1), b=bx>>(1+6);
    int d=half*128+threadIdx.x;
    float Av[16]; bool ok=true;
    #pragma unroll
    for(int s=0;s<16;s++){
        float av=-__expf(A_log[d*16+s]); Av[s]=av;
        ok = ok && (fabsf(av+(float)(s+1))<1e-4f);
    }
    float h[16],P[16];
    #pragma unroll
    for(int s=0;s<16;s++){ h[s]=0.f; P[s]=1.f; }
    int row0=b*LQ+chunk*CLEN;
    const float* dtp=dt+(size_t)row0*256+d;
    const float* xcp=xc+(size_t)row0*256+d;
    #pragma unroll 2
    for(int t=0;t<CLEN;t++){
        float dtv=dtp[t*256], xcv=xcp[t*256];
        const float* br=dbc+(size_t)(row0+t)*40+8;
        float4 q0=*(const float4*)br, q1=*(const float4*)(br+4);
        float4 q2=*(const float4*)(br+8), q3=*(const float4*)(br+12);
        float bc[16]={q0.x,q0.y,q0.z,q0.w,q1.x,q1.y,q1.z,q1.w,
                      q2.x,q2.y,q2.z,q2.w,q3.x,q3.y,q3.z,q3.w};
        float a[16];
        if(ok){
            float e1=__expf(-dtv);
            a[0]=e1;
            #pragma unroll
            for(int s=1;s<16;s++) a[s]=a[s-1]*e1;
        }else{
            #pragma unroll
            for(int s=0;s<16;s++) a[s]=__expf(dtv*Av[s]);
        }
        float dx=dtv*xcv;
        #pragma unroll
        for(int s=0;s<16;s++){ h[s]=fmaf(a[s],h[s],dx*bc[s]); P[s]*=a[s]; }
    }
    size_t ci=((size_t)(b*256+d)*NC+chunk)*16;
    #pragma unroll
    for(int s=0;s<16;s+=4){
        *(float4*)&cP[ci+s]=make_float4(P[s],P[s+1],P[s+2],P[s+3]);
        *(float4*)&cE[ci+s]=make_float4(h[s],h[s+1],h[s+2],h[s+3]);
    }
}

__global__ void k_scan2(const float* __restrict__ P, const float* __restrict__ E,
                        float* __restrict__ Hi){
    int gid=blockIdx.x*256+threadIdx.x;
    int s=gid&15, bd=gid>>4;
    size_t base=(size_t)bd*NC*16+s;
    float h=0.f;
    #pragma unroll 8
    for(int c=0;c<NC;c++){
        Hi[base+c*16]=h;
        h = P[base+c*16]*h + E[base+c*16];
    }
}

__global__ __launch_bounds__(128,4) void k_scan3(const float* __restrict__ dt,
        const float* __restrict__ xc, const float* __restrict__ dbc,
        const float* __restrict__ A_log, const float* __restrict__ Hi,
        const float* __restrict__ xz, const float* __restrict__ D_,
        float* __restrict__ y){
    int bx=blockIdx.x;
    int half=bx&1, chunk=(bx>>1)&(NC-1), b=bx>>(1+6);
    int d=half*128+threadIdx.x;
    float Av[16]; bool ok=true;
    #pragma unroll
    for(int s=0;s<16;s++){
        float av=-__expf(A_log[d*16+s]); Av[s]=av;
        ok = ok && (fabsf(av+(float)(s+1))<1e-4f);
    }
    float Dv=D_[d];
    float h[16];
    size_t ci=((size_t)(b*256+d)*NC+chunk)*16;
    #pragma unroll
    for(int s=0;s<16;s+=4){
        float4 q=*(const float4*)&Hi[ci+s];
        h[s]=q.x; h[s+1]=q.y; h[s+2]=q.z; h[s+3]=q.w;
    }
    int row0=b*LQ+chunk*CLEN;
    const float* dtp=dt+(size_t)row0*256+d;
    const float* xcp=xc+(size_t)row0*256+d;
    const float* zp =xz+(size_t)row0*512+256+d;
    float* yp=y+(size_t)row0*256+d;
    #pragma unroll 2
    for(int t=0;t<CLEN;t++){
        float dtv=dtp[t*256], xcv=xcp[t*256];
        const float* br=dbc+(size_t)(row0+t)*40+8;
        float4 q0=*(const float4*)br, q1=*(const float4*)(br+4);
        float4 q2=*(const float4*)(br+8), q3=*(const float4*)(br+12);
        float4 c0=*(const float4*)(br+16), c1=*(const float4*)(br+20);
        float4 c2=*(const float4*)(br+24), c3=*(const float4*)(br+28);
        float bc[16]={q0.x,q0.y,q0.z,q0.w,q1.x,q1.y,q1.z,q1.w,
                      q2.x,q2.y,q2.z,q2.w,q3.x,q3.y,q3.z,q3.w};
        float cc[16]={c0.x,c0.y,c0.z,c0.w,c1.x,c1.y,c1.z,c1.w,
                      c2.x,c2.y,c2.z,c2.w,c3.x,c3.y,c3.z,c3.w};
        float a[16];
        if(ok){
            float e1=__expf(-dtv);
            a[0]=e1;
            #pragma unroll
            for(int s=1;s<16;s++) a[s]=a[s-1]*e1;
        }else{
            #pragma unroll
            for(int s=0;s<16;s++) a[s]=__expf(dtv*Av[s]);
        }
        float dx=dtv*xcv;
        float accy=0.f;
        #pragma unroll
        for(int s=0;s<16;s++){
            h[s]=fmaf(a[s],h[s],dx*bc[s]);
            accy=fmaf(h[s],cc[s],accy);
        }
        yp[t*256] = (accy + Dv*xcv) * zp[t*512];
    }
}

extern "C" void kernel_launch(void* const* d_in, const int* in_sizes, int n_in,
                              void* d_out, int out_size){
    const float* x        =(const float*)d_in[0];
    const float* pe       =(const float*)d_in[1];
    const float* norm_g   =(const float*)d_in[2];
    const float* norm_b   =(const float*)d_in[3];
    const float* conv1_w  =(const float*)d_in[4];
    const float* conv1_b  =(const float*)d_in[5];
    const float* ca1_w    =(const float*)d_in[6];
    const float* ca2_w    =(const float*)d_in[7];
    const float* conv2_w  =(const float*)d_in[8];
    const float* conv2_b  =(const float*)d_in[9];
    const float* head_w   =(const float*)d_in[10];
    const float* head_b   =(const float*)d_in[11];
    const float* in_proj_w=(const float*)d_in[12];
    const float* conv1d_w =(const float*)d_in[13];
    const float* conv1d_b =(const float*)d_in[14];
    const float* x_proj_w =(const float*)d_in[15];
    const float* dt_proj_w=(const float*)d_in[16];
    const float* dt_proj_b=(const float*)d_in[17];
    const float* A_log    =(const float*)d_in[18];
    const float* D_       =(const float*)d_in[19];
    const float* out_proj_w=(const float*)d_in[20];
    float* out=(float*)d_out;

    static bool init_done=false;
    static cudaStream_t s1, s2;
    static cudaEvent_t evA, evPV, evT;
    if(!init_done){
        cudaFuncSetAttribute(k_xproj, cudaFuncAttributeMaxDynamicSharedMemorySize, 90000);
        cudaStreamCreateWithFlags(&s1, cudaStreamNonBlocking);
        cudaStreamCreateWithFlags(&s2, cudaStreamNonBlocking);
        cudaEventCreateWithFlags(&evA, cudaEventDisableTiming);
        cudaEventCreateWithFlags(&evPV, cudaEventDisableTiming);
        cudaEventCreateWithFlags(&evT, cudaEventDisableTiming);
        init_done=true;
    }

    float *feat,*pv,*casum,*ca,*sacc,*xT,*x1n,*xz,*xc,*dbc,*dt;
    float *cP,*cE,*Hi,*y; int* order;
    cudaGetSymbolAddress((void**)&feat, g_feat);
    cudaGetSymbolAddress((void**)&pv, g_pvterm);
    cudaGetSymbolAddress((void**)&casum, g_casum);
    cudaGetSymbolAddress((void**)&ca, g_ca);
    cudaGetSymbolAddress((void**)&sacc, g_scores);
    cudaGetSymbolAddress((void**)&order, g_order);
    cudaGetSymbolAddress((void**)&xT, g_xT);
    cudaGetSymbolAddress((void**)&x1n, g_x1n);
    cudaGetSymbolAddress((void**)&xz, g_xz);
    cudaGetSymbolAddress((void**)&xc, g_xc);
    cudaGetSymbolAddress((void**)&dbc, g_dbc);
    cudaGetSymbolAddress((void**)&dt, g_dt);
    cudaGetSymbolAddress((void**)&cP, g_cP);
    cudaGetSymbolAddress((void**)&cE, g_cE);
    cudaGetSymbolAddress((void**)&Hi, g_hinit);
    cudaGetSymbolAddress((void**)&y, g_y);

    // fork: pv on s1, transpose on s2, conv chain on default stream
    cudaEventRecord(evA, 0);
    cudaStreamWaitEvent(s1, evA, 0);
    cudaStreamWaitEvent(s2, evA, 0);

    k_pv<<<64,256,0,s1>>>(x, pv, sacc);
    cudaEventRecord(evPV, s1);

    k_transpose<<<dim3(128,4,4),dim3(32,8),0,s2>>>(x, xT);
    cudaEventRecord(evT, s2);

    k_conv1<<<512,256>>>(x, conv1_w, conv1_b, feat, casum);
    k_ca<<<1,128>>>(casum, ca1_w, ca2_w, ca);
    cudaStreamWaitEvent(0, evPV, 0);   // sacc zeroed before score2 atomics
    k_score2<<<512,256>>>(feat, ca, conv2_w, conv2_b, head_w, sacc);
    k_sort<<<4,256>>>(sacc, pv, head_b, order);
    cudaStreamWaitEvent(0, evT, 0);    // xT ready before gather
    k_gather_ln<<<2048,256>>>(xT, pe, order, norm_g, norm_b, x1n);
    gemm_tf32<<<dim3(4,128),256>>>(x1n, in_proj_w, xz, 16384, 512, 128, 256, 0, 0);
    k_xproj<<<512,256,88000>>>(xz, conv1d_w, conv1d_b, x_proj_w, dt_proj_w,
                               dt_proj_b, xc, dbc, dt);
    k_scan1<<<512,128>>>(dt, xc, dbc, A_log, cP, cE);
    k_scan2<<<64,256>>>(cP, cE, Hi);
    k_scan3<<<512,128>>>(dt, xc, dbc, A_log, Hi, xz, D_, y);
    gemm_tf32<<<dim3(1,128),256>>>(y, out_proj_w, out, 16384, 128, 256, 1<<30,
                                   order, 1);
}

// round 16
// speedup vs baseline: 1.5779x; 1.0509x over previous
#include <cuda_runtime.h>
#include <math.h>
#include <stdint.h>

#define LQ 4096
#define NC 64
#define CLEN 64

__device__ float g_feat[4*128*4096];
__device__ float g_pvterm[4*4096];
__device__ float g_casum[4*128];
__device__ float g_ca[4*128];
__device__ float g_scores[4*4096];
__device__ int   g_order[4*4096];
__device__ float g_xT[4*4096*128];
__device__ float g_x1n[4*4096*128];
__device__ float g_xz[4*4096*512];
__device__ float g_xc[4*4096*256];
__device__ float g_dbc[4*4096*40];
__device__ float g_dt[4*4096*256];
__device__ float g_cP[4*256*NC*16];
__device__ float g_cE[4*256*NC*16];
__device__ float g_hinit[4*256*NC*16];
__device__ float g_y[4*4096*256];

__device__ __forceinline__ float sigmf(float x){ return 1.f/(1.f+__expf(-x)); }
__device__ __forceinline__ float geluf(float x){ return 0.5f*x*(1.f+erff(x*0.70710678f)); }
__device__ __forceinline__ float warp_sum(float v){
    v += __shfl_xor_sync(~0u,v,16); v += __shfl_xor_sync(~0u,v,8);
    v += __shfl_xor_sync(~0u,v,4);  v += __shfl_xor_sync(~0u,v,2);
    v += __shfl_xor_sync(~0u,v,1);  return v;
}
__device__ __forceinline__ uint32_t f2tf(float f){
    uint32_t r; asm("cvt.rna.tf32.f32 %0, %1;" : "=r"(r) : "f"(f)); return r;
}

__global__ void k_pv(const float* __restrict__ x, float* __restrict__ pv,
                     float* __restrict__ sacc){
    int p = blockIdx.x*256+threadIdx.x;
    int b = p>>12, hw = p&4095;
    const float* xp = x + (size_t)b*128*LQ + hw;
    float s=0.f,s2=0.f;
    #pragma unroll 8
    for(int c=0;c<128;c++){ float v=xp[c*LQ]; s+=v; s2+=v*v; }
    float var = (s2 - s*s*(1.f/128.f))*(1.f/127.f);
    pv[p] = 0.3f*sigmf(10.f*var);
    sacc[p] = 0.f;
}

__global__ __launch_bounds__(256) void k_conv1(const float* __restrict__ x,
        const float* __restrict__ w_, const float* __restrict__ b_,
        float* __restrict__ feat, float* __restrict__ casum){
    __shared__ float pl[4096]; __shared__ float rs[8];
    int bc = blockIdx.x, c = bc&127, tid = threadIdx.x;
    const float* xp = x + (size_t)bc*4096;
    for(int i=tid;i<1024;i+=256) ((float4*)pl)[i] = ((const float4*)xp)[i];
    float w[9];
    #pragma unroll
    for(int q=0;q<9;q++) w[q]=w_[c*9+q];
    float bias=b_[c];
    __syncthreads();
    float lsum=0.f;
    #pragma unroll 4
    for(int i=0;i<16;i++){
        int p=tid+i*256, h=p>>6, ww=p&63;
        float s=bias;
        #pragma unroll
        for(int dy=-1;dy<=1;dy++){ int hh=h+dy; if((unsigned)hh<64u){
            #pragma unroll
            for(int dx=-1;dx<=1;dx++){ int wn=ww+dx; if((unsigned)wn<64u)
                s += w[(dy+1)*3+dx+1]*pl[hh*64+wn]; } } }
        float g=geluf(s);
        feat[(size_t)bc*4096+p]=g; lsum+=g;
    }
    lsum=warp_sum(lsum);
    if((tid&31)==0) rs[tid>>5]=lsum;
    __syncthreads();
    if(tid==0){ float t=0.f; for(int q=0;q<8;q++) t+=rs[q]; casum[bc]=t; }
}

// one block per batch; warp-parallel hidden layer, coalesced weight reads
__global__ __launch_bounds__(256) void k_ca(const float* __restrict__ casum,
        const float* __restrict__ w1, const float* __restrict__ w2,
        float* __restrict__ ca){
    __shared__ float mean[128]; __shared__ float hid[32];
    int b=blockIdx.x, tid=threadIdx.x, lane=tid&31, warp=tid>>5;
    if(tid<128) mean[tid]=casum[b*128+tid]*(1.f/4096.f);
    __syncthreads();
    float4 mv=*(const float4*)&mean[lane*4];
    #pragma unroll
    for(int q=0;q<4;q++){
        int j=warp*4+q;
        float4 wv=*(const float4*)&w1[j*128+lane*4];
        float p=wv.x*mv.x+wv.y*mv.y+wv.z*mv.z+wv.w*mv.w;
        p=warp_sum(p);
        if(lane==0) hid[j]=fmaxf(p,0.f);
    }
    __syncthreads();
    if(tid<128){
        float v=0.f;
        const float* wr=&w2[tid*32];
        #pragma unroll
        for(int j=0;j<32;j+=4){
            float4 w4=*(const float4*)&wr[j];
            v += hid[j]*w4.x + hid[j+1]*w4.y + hid[j+2]*w4.z + hid[j+3]*w4.w;
        }
        ca[b*128+tid]=sigmf(v);
    }
}

__global__ __launch_bounds__(256) void k_score2(const float* __restrict__ feat,
        const float* __restrict__ ca, const float* __restrict__ w2_,
        const float* __restrict__ b2_, const float* __restrict__ hw_,
        float* __restrict__ sacc){
    __shared__ float pl[4096];
    int bc=blockIdx.x, b=bc>>7, c=bc&127, tid=threadIdx.x;
    const float* fp=feat+(size_t)bc*4096;
    for(int i=tid;i<1024;i+=256) ((float4*)pl)[i]=((const float4*)fp)[i];
    float w[9];
    #pragma unroll
    for(int q=0;q<9;q++) w[q]=w2_[c*9+q];
    float cav=ca[bc], bias=b2_[c], hwc=hw_[c];
    __syncthreads();
    #pragma unroll 4
    for(int i=0;i<16;i++){
        int p=tid+i*256, h=p>>6, ww=p&63;
        float s=0.f;
        #pragma unroll
        for(int dy=-1;dy<=1;dy++){ int hh=h+dy; if((unsigned)hh<64u){
            #pragma unroll
            for(int dx=-1;dx<=1;dx++){ int wn=ww+dx; if((unsigned)wn<64u)
                s += w[(dy+1)*3+dx+1]*pl[hh*64+wn]; } } }
        float v = cav*s + bias;
        atomicAdd(&sacc[b*4096+p], geluf(v)*hwc);
    }
}

__global__ void k_sort(const float* __restrict__ sacc, const float* __restrict__ pv,
                       const float* __restrict__ hb_, int* __restrict__ order){
    __shared__ float sm[256];
    int b=blockIdx.x, p=threadIdx.x, py=p>>4, px=p&15;
    float hb0=hb_[0];
    float s=0.f;
    #pragma unroll
    for(int r=0;r<4;r++)
        #pragma unroll
        for(int cx=0;cx<4;cx++){
            int pix=(py*4+r)*64+px*4+cx;
            s += 0.7f*sigmf(sacc[b*4096+pix]+hb0) + pv[b*4096+pix];
        }
    sm[p]=s;
    __syncthreads();
    float mys=sm[p]; int rank=0;
    for(int j=0;j<256;j++){ float o=sm[j]; rank += (o>mys)||(o==mys && j<p); }
    #pragma unroll
    for(int j=0;j<16;j++){
        int pix=(py*4+(j>>2))*64 + px*4 + (j&3);
        order[b*4096+rank*16+j]=pix;
    }
}

__global__ void k_transpose(const float* __restrict__ x, float* __restrict__ xT){
    __shared__ float tile[32][33];
    int b=blockIdx.z, c0=blockIdx.y*32, p0=blockIdx.x*32;
    int tx=threadIdx.x, ty=threadIdx.y;
    for(int i=0;i<32;i+=8)
        tile[ty+i][tx] = x[((size_t)(b*128+c0+ty+i))*4096 + p0+tx];
    __syncthreads();
    for(int i=0;i<32;i+=8)
        xT[((size_t)(b*4096+p0+ty+i))*128 + c0+tx] = tile[tx][ty+i];
}

__global__ __launch_bounds__(256) void k_gather_ln(const float* __restrict__ xT,
        const float* __restrict__ pe, const int* __restrict__ order,
        const float* __restrict__ g_, const float* __restrict__ bn_,
        float* __restrict__ out){
    int warp=threadIdx.x>>5, lane=threadIdx.x&31;
    int token=blockIdx.x*8+warp, b=token>>12;
    int pix=order[token];
    float4 v=*(const float4*)&xT[((size_t)(b*4096+pix))*128+lane*4];
    float4 p=*(const float4*)&pe[pix*128+lane*4];
    v.x+=p.x; v.y+=p.y; v.z+=p.z; v.w+=p.w;
    float s=v.x+v.y+v.z+v.w;
    float s2=v.x*v.x+v.y*v.y+v.z*v.z+v.w*v.w;
    s=warp_sum(s); s2=warp_sum(s2);
    float mu=s*(1.f/128.f);
    float rstd=rsqrtf(s2*(1.f/128.f)-mu*mu+1e-5f);
    float4 g4=*(const float4*)&g_[lane*4];
    float4 b4=*(const float4*)&bn_[lane*4];
    float4 o;
    o.x=(v.x-mu)*rstd*g4.x+b4.x; o.y=(v.y-mu)*rstd*g4.y+b4.y;
    o.z=(v.z-mu)*rstd*g4.z+b4.z; o.w=(v.w-mu)*rstd*g4.w+b4.w;
    *(float4*)&out[(size_t)token*128+lane*4]=o;
}

#define GSTR 140
__global__ __launch_bounds__(256) void gemm_tf32(const float* __restrict__ A,
        const float* __restrict__ Bw, float* __restrict__ C, int M,int N,int K,
        int silu_from, const int* __restrict__ ord, int do_scatter){
    __shared__ uint32_t As[2][16][GSTR];
    __shared__ uint32_t Bs[2][16][GSTR];
    const int bm=blockIdx.y*128, bn=blockIdx.x*128;
    const int tid=threadIdx.x, lane=tid&31, warp=tid>>5;
    const int wm=(warp&1)*64, wn=(warp>>1)*32;
    const int g=lane>>2, tg=lane&3;
    const int lr=tid>>2, lq=(tid&3)*4;
    float acc[4][4][4];
    #pragma unroll
    for(int i=0;i<4;i++)
        #pragma unroll
        for(int j=0;j<4;j++)
            #pragma unroll
            for(int q=0;q<4;q++) acc[i][j][q]=0.f;
    const float* Ag = A + (size_t)(bm+lr)*K + lq;
    const float* Bg = Bw + (size_t)(bn+lr)*K + lq;
    const size_t sk64 = (size_t)64*K;
    float4 ra0,ra1,rb0,rb1;
    ra0=*(const float4*)(Ag); ra1=*(const float4*)(Ag+sk64);
    rb0=*(const float4*)(Bg); rb1=*(const float4*)(Bg+sk64);
    {
        As[0][lq+0][lr]=f2tf(ra0.x); As[0][lq+1][lr]=f2tf(ra0.y);
        As[0][lq+2][lr]=f2tf(ra0.z); As[0][lq+3][lr]=f2tf(ra0.w);
        As[0][lq+0][lr+64]=f2tf(ra1.x); As[0][lq+1][lr+64]=f2tf(ra1.y);
        As[0][lq+2][lr+64]=f2tf(ra1.z); As[0][lq+3][lr+64]=f2tf(ra1.w);
        Bs[0][lq+0][lr]=f2tf(rb0.x); Bs[0][lq+1][lr]=f2tf(rb0.y);
        Bs[0][lq+2][lr]=f2tf(rb0.z); Bs[0][lq+3][lr]=f2tf(rb0.w);
        Bs[0][lq+0][lr+64]=f2tf(rb1.x); Bs[0][lq+1][lr+64]=f2tf(rb1.y);
        Bs[0][lq+2][lr+64]=f2tf(rb1.z); Bs[0][lq+3][lr+64]=f2tf(rb1.w);
    }
    __syncthreads();
    const int nk=K>>4;
    for(int kt=0;kt<nk;kt++){
        const int cur=kt&1;
        if(kt+1<nk){
            ra0=*(const float4*)(Ag+(kt+1)*16);
            ra1=*(const float4*)(Ag+sk64+(kt+1)*16);
            rb0=*(const float4*)(Bg+(kt+1)*16);
            rb1=*(const float4*)(Bg+sk64+(kt+1)*16);
        }
        #pragma unroll
        for(int ks=0;ks<2;ks++){
            uint32_t af[4][4], bf[4][2];
            #pragma unroll
            for(int i=0;i<4;i++){
                int row=wm+16*i+g;
                af[i][0]=As[cur][ks*8+tg][row];
                af[i][1]=As[cur][ks*8+tg][row+8];
                af[i][2]=As[cur][ks*8+tg+4][row];
                af[i][3]=As[cur][ks*8+tg+4][row+8];
            }
            #pragma unroll
            for(int j=0;j<4;j++){
                int col=wn+8*j+g;
                bf[j][0]=Bs[cur][ks*8+tg][col];
                bf[j][1]=Bs[cur][ks*8+tg+4][col];
            }
            #pragma unroll
            for(int i=0;i<4;i++)
                #pragma unroll
                for(int j=0;j<4;j++){
                    asm volatile(
                      "mma.sync.aligned.m16n8k8.row.col.f32.tf32.tf32.f32 "
                      "{%0,%1,%2,%3},{%4,%5,%6,%7},{%8,%9},{%0,%1,%2,%3};"
                      : "+f"(acc[i][j][0]),"+f"(acc[i][j][1]),
                        "+f"(acc[i][j][2]),"+f"(acc[i][j][3])
                      : "r"(af[i][0]),"r"(af[i][1]),"r"(af[i][2]),"r"(af[i][3]),
                        "r"(bf[j][0]),"r"(bf[j][1]));
                }
        }
        if(kt+1<nk){
            const int nb=(kt+1)&1;
            As[nb][lq+0][lr]=f2tf(ra0.x); As[nb][lq+1][lr]=f2tf(ra0.y);
            As[nb][lq+2][lr]=f2tf(ra0.z); As[nb][lq+3][lr]=f2tf(ra0.w);
            As[nb][lq+0][lr+64]=f2tf(ra1.x); As[nb][lq+1][lr+64]=f2tf(ra1.y);
            As[nb][lq+2][lr+64]=f2tf(ra1.z); As[nb][lq+3][lr+64]=f2tf(ra1.w);
            Bs[nb][lq+0][lr]=f2tf(rb0.x); Bs[nb][lq+1][lr]=f2tf(rb0.y);
            Bs[nb][lq+2][lr]=f2tf(rb0.z); Bs[nb][lq+3][lr]=f2tf(rb0.w);
            Bs[nb][lq+0][lr+64]=f2tf(rb1.x); Bs[nb][lq+1][lr+64]=f2tf(rb1.y);
            Bs[nb][lq+2][lr+64]=f2tf(rb1.z); Bs[nb][lq+3][lr+64]=f2tf(rb1.w);
        }
        __syncthreads();
    }
    if(do_scatter){
        #pragma unroll
        for(int i=0;i<4;i++){
            int row=bm+wm+16*i+g;
            int b=row>>12;
            int p1=ord[row], p2=ord[row+8];
            #pragma unroll
            for(int j=0;j<4;j++){
                int col=bn+wn+8*j+2*tg;
                float* o1=C+((size_t)(b*128+col))*4096;
                float* o2=C+((size_t)(b*128+col+1))*4096;
                o1[p1]=acc[i][j][0]; o2[p1]=acc[i][j][1];
                o1[p2]=acc[i][j][2]; o2[p2]=acc[i][j][3];
            }
        }
    }else{
        #pragma unroll
        for(int i=0;i<4;i++)
            #pragma unroll
            for(int j=0;j<4;j++){
                int row=bm+wm+16*i+g, col=bn+wn+8*j+2*tg;
                float4 o=make_float4(acc[i][j][0],acc[i][j][1],acc[i][j][2],acc[i][j][3]);
                if(col>=silu_from){
                    o.x*=sigmf(o.x); o.y*=sigmf(o.y);
                    o.z*=sigmf(o.z); o.w*=sigmf(o.w);
                }
                float* cp=C+(size_t)row*N+col;
                *(float2*)cp = make_float2(o.x,o.y);
                *(float2*)(cp+(size_t)8*N) = make_float2(o.z,o.w);
            }
    }
}

#define XSTR 260
extern __shared__ float smemx[];
__global__ __launch_bounds__(256) void k_xproj(const float* __restrict__ xz,
        const float* __restrict__ cw, const float* __restrict__ cb,
        const float* __restrict__ xpw, const float* __restrict__ dpw,
        const float* __restrict__ dpb, float* __restrict__ xcg,
        float* __restrict__ dbc, float* __restrict__ dtout){
    float* Ws = smemx;
    float* Xm = smemx + 40*XSTR;
    float* dpws = smemx + 75*XSTR;
    float* dtl  = dpws + 2048;
    int tid=threadIdx.x, tok0=blockIdx.x*32;
    int l0=tok0&4095;
    for(int i=tid;i<2560;i+=256){
        int r=i>>6, c4=(i&63)<<2;
        float4 v=*(const float4*)&xpw[r*256+c4];
        float* dst=&Ws[r*XSTR+c4];
        dst[0]=v.x; dst[1]=v.y; dst[2]=v.z; dst[3]=v.w;
    }
    for(int i=tid;i<2240;i+=256){
        int r=i>>6, c4=(i&63)<<2;
        float4 v=make_float4(0.f,0.f,0.f,0.f);
        if(l0+r>=3) v=*(const float4*)&xz[((size_t)(tok0-3+r))*512+c4];
        float* dst=&Xm[r*XSTR+c4];
        dst[0]=v.x; dst[1]=v.y; dst[2]=v.z; dst[3]=v.w;
    }
    for(int i=tid;i<2048;i+=256) dpws[i]=dpw[i];
    __syncthreads();
    {
        int c=tid;
        float4 wv=*(const float4*)&cw[c*4];
        float bias=cb[c];
        float xm0=Xm[0*XSTR+c], xm1=Xm[1*XSTR+c], xm2=Xm[2*XSTR+c];
        float xcr[32];
        #pragma unroll
        for(int t=0;t<32;t++){
            float xm3=Xm[(t+3)*XSTR+c];
            float a=bias + wv.x*xm0 + wv.y*xm1 + wv.z*xm2 + wv.w*xm3;
            xcr[t]=a/(1.f+__expf(-a));
            xm0=xm1; xm1=xm2; xm2=xm3;
        }
        __syncthreads();
        #pragma unroll
        for(int t=0;t<32;t++){
            Xm[(t+3)*XSTR+c]=xcr[t];
            xcg[((size_t)(tok0+t))*256+c]=xcr[t];
        }
    }
    __syncthreads();
    int tok=tid>>3, ng=tid&7;
    float acc[5]={0.f,0.f,0.f,0.f,0.f};
    const float* xr = Xm + (tok+3)*XSTR;
    for(int k=0;k<256;k+=4){
        float4 xv=*(const float4*)(xr+k);
        #pragma unroll
        for(int j=0;j<5;j++){
            float4 wv=*(const float4*)(Ws+(ng+8*j)*XSTR+k);
            acc[j]=fmaf(xv.x,wv.x,acc[j]); acc[j]=fmaf(xv.y,wv.y,acc[j]);
            acc[j]=fmaf(xv.z,wv.z,acc[j]); acc[j]=fmaf(xv.w,wv.w,acc[j]);
        }
    }
    #pragma unroll
    for(int j=0;j<5;j++) dbc[((size_t)(tok0+tok))*40 + ng+8*j] = acc[j];
    dtl[tok*8+ng]=acc[0];
    __syncthreads();
    float dl[8];
    #pragma unroll
    for(int q=0;q<8;q++) dl[q]=dtl[tok*8+q];
    int dbase=(tid&7)*32;
    float* dto = dtout + (size_t)(tok0+tok)*256;
    for(int jj=0;jj<32;jj++){
        int d=dbase+jj;
        float a=dpb[d];
        const float* wr=&dpws[d*8];
        #pragma unroll
        for(int q=0;q<8;q++) a += dl[q]*wr[q];
        dto[d] = (a>20.f)? a : log1pf(__expf(a));
    }
}

__global__ __launch_bounds__(128,4) void k_scan1(const float* __restrict__ dt,
        const float* __restrict__ xc, const float* __restrict__ dbc,
        const float* __restrict__ A_log, float* __restrict__ cP, float* __restrict__ cE){
    int bx=blockIdx.x;
    int half=bx&1, chunk=(bx>>1)&(NC-1), b=bx>>(1+6);
    int d=half*128+threadIdx.x;
    float Av[16]; bool ok=true;
    #pragma unroll
    for(int s=0;s<16;s++){
        float av=-__expf(A_log[d*16+s]); Av[s]=av;
        ok = ok && (fabsf(av+(float)(s+1))<1e-4f);
    }
    float h[16],P[16];
    #pragma unroll
    for(int s=0;s<16;s++){ h[s]=0.f; P[s]=1.f; }
    int row0=b*LQ+chunk*CLEN;
    const float* dtp=dt+(size_t)row0*256+d;
    const float* xcp=xc+(size_t)row0*256+d;
    #pragma unroll 2
    for(int t=0;t<CLEN;t++){
        float dtv=dtp[t*256], xcv=xcp[t*256];
        const float* br=dbc+(size_t)(row0+t)*40+8;
        float4 q0=*(const float4*)br, q1=*(const float4*)(br+4);
        float4 q2=*(const float4*)(br+8), q3=*(const float4*)(br+12);
        float bc[16]={q0.x,q0.y,q0.z,q0.w,q1.x,q1.y,q1.z,q1.w,
                      q2.x,q2.y,q2.z,q2.w,q3.x,q3.y,q3.z,q3.w};
        float a[16];
        if(ok){
            float e1=__expf(-dtv);
            a[0]=e1;
            #pragma unroll
            for(int s=1;s<16;s++) a[s]=a[s-1]*e1;
        }else{
            #pragma unroll
            for(int s=0;s<16;s++) a[s]=__expf(dtv*Av[s]);
        }
        float dx=dtv*xcv;
        #pragma unroll
        for(int s=0;s<16;s++){ h[s]=fmaf(a[s],h[s],dx*bc[s]); P[s]*=a[s]; }
    }
    size_t ci=((size_t)(b*256+d)*NC+chunk)*16;
    #pragma unroll
    for(int s=0;s<16;s+=4){
        *(float4*)&cP[ci+s]=make_float4(P[s],P[s+1],P[s+2],P[s+3]);
        *(float4*)&cE[ci+s]=make_float4(h[s],h[s+1],h[s+2],h[s+3]);
    }
}

__global__ void k_scan2(const float* __restrict__ P, const float* __restrict__ E,
                        float* __restrict__ Hi){
    int gid=blockIdx.x*256+threadIdx.x;
    int s=gid&15, bd=gid>>4;
    size_t base=(size_t)bd*NC*16+s;
    float h=0.f;
    #pragma unroll 8
    for(int c=0;c<NC;c++){
        Hi[base+c*16]=h;
        h = P[base+c*16]*h + E[base+c*16];
    }
}

__global__ __launch_bounds__(128,4) void k_scan3(const float* __restrict__ dt,
        const float* __restrict__ xc, const float* __restrict__ dbc,
        const float* __restrict__ A_log, const float* __restrict__ Hi,
        const float* __restrict__ xz, const float* __restrict__ D_,
        float* __restrict__ y){
    int bx=blockIdx.x;
    int half=bx&1, chunk=(bx>>1)&(NC-1), b=bx>>(1+6);
    int d=half*128+threadIdx.x;
    float Av[16]; bool ok=true;
    #pragma unroll
    for(int s=0;s<16;s++){
        float av=-__expf(A_log[d*16+s]); Av[s]=av;
        ok = ok && (fabsf(av+(float)(s+1))<1e-4f);
    }
    float Dv=D_[d];
    float h[16];
    size_t ci=((size_t)(b*256+d)*NC+chunk)*16;
    #pragma unroll
    for(int s=0;s<16;s+=4){
        float4 q=*(const float4*)&Hi[ci+s];
        h[s]=q.x; h[s+1]=q.y; h[s+2]=q.z; h[s+3]=q.w;
    }
    int row0=b*LQ+chunk*CLEN;
    const float* dtp=dt+(size_t)row0*256+d;
    const float* xcp=xc+(size_t)row0*256+d;
    const float* zp =xz+(size_t)row0*512+256+d;
    float* yp=y+(size_t)row0*256+d;
    #pragma unroll 2
    for(int t=0;t<CLEN;t++){
        float dtv=dtp[t*256], xcv=xcp[t*256];
        const float* br=dbc+(size_t)(row0+t)*40+8;
        float4 q0=*(const float4*)br, q1=*(const float4*)(br+4);
        float4 q2=*(const float4*)(br+8), q3=*(const float4*)(br+12);
        float4 c0=*(const float4*)(br+16), c1=*(const float4*)(br+20);
        float4 c2=*(const float4*)(br+24), c3=*(const float4*)(br+28);
        float bc[16]={q0.x,q0.y,q0.z,q0.w,q1.x,q1.y,q1.z,q1.w,
                      q2.x,q2.y,q2.z,q2.w,q3.x,q3.y,q3.z,q3.w};
        float cc[16]={c0.x,c0.y,c0.z,c0.w,c1.x,c1.y,c1.z,c1.w,
                      c2.x,c2.y,c2.z,c2.w,c3.x,c3.y,c3.z,c3.w};
        float a[16];
        if(ok){
            float e1=__expf(-dtv);
            a[0]=e1;
            #pragma unroll
            for(int s=1;s<16;s++) a[s]=a[s-1]*e1;
        }else{
            #pragma unroll
            for(int s=0;s<16;s++) a[s]=__expf(dtv*Av[s]);
        }
        float dx=dtv*xcv;
        float accy=0.f;
        #pragma unroll
        for(int s=0;s<16;s++){
            h[s]=fmaf(a[s],h[s],dx*bc[s]);
            accy=fmaf(h[s],cc[s],accy);
        }
        yp[t*256] = (accy + Dv*xcv) * zp[t*512];
    }
}

extern "C" void kernel_launch(void* const* d_in, const int* in_sizes, int n_in,
                              void* d_out, int out_size){
    const float* x        =(const float*)d_in[0];
    const float* pe       =(const float*)d_in[1];
    const float* norm_g   =(const float*)d_in[2];
    const float* norm_b   =(const float*)d_in[3];
    const float* conv1_w  =(const float*)d_in[4];
    const float* conv1_b  =(const float*)d_in[5];
    const float* ca1_w    =(const float*)d_in[6];
    const float* ca2_w    =(const float*)d_in[7];
    const float* conv2_w  =(const float*)d_in[8];
    const float* conv2_b  =(const float*)d_in[9];
    const float* head_w   =(const float*)d_in[10];
    const float* head_b   =(const float*)d_in[11];
    const float* in_proj_w=(const float*)d_in[12];
    const float* conv1d_w =(const float*)d_in[13];
    const float* conv1d_b =(const float*)d_in[14];
    const float* x_proj_w =(const float*)d_in[15];
    const float* dt_proj_w=(const float*)d_in[16];
    const float* dt_proj_b=(const float*)d_in[17];
    const float* A_log    =(const float*)d_in[18];
    const float* D_       =(const float*)d_in[19];
    const float* out_proj_w=(const float*)d_in[20];
    float* out=(float*)d_out;

    static bool init_done=false;
    static cudaStream_t s1, s2;
    static cudaEvent_t evA, evPV, evT;
    if(!init_done){
        cudaFuncSetAttribute(k_xproj, cudaFuncAttributeMaxDynamicSharedMemorySize, 90000);
        cudaStreamCreateWithFlags(&s1, cudaStreamNonBlocking);
        cudaStreamCreateWithFlags(&s2, cudaStreamNonBlocking);
        cudaEventCreateWithFlags(&evA, cudaEventDisableTiming);
        cudaEventCreateWithFlags(&evPV, cudaEventDisableTiming);
        cudaEventCreateWithFlags(&evT, cudaEventDisableTiming);
        init_done=true;
    }

    float *feat,*pv,*casum,*ca,*sacc,*xT,*x1n,*xz,*xc,*dbc,*dt;
    float *cP,*cE,*Hi,*y; int* order;
    cudaGetSymbolAddress((void**)&feat, g_feat);
    cudaGetSymbolAddress((void**)&pv, g_pvterm);
    cudaGetSymbolAddress((void**)&casum, g_casum);
    cudaGetSymbolAddress((void**)&ca, g_ca);
    cudaGetSymbolAddress((void**)&sacc, g_scores);
    cudaGetSymbolAddress((void**)&order, g_order);
    cudaGetSymbolAddress((void**)&xT, g_xT);
    cudaGetSymbolAddress((void**)&x1n, g_x1n);
    cudaGetSymbolAddress((void**)&xz, g_xz);
    cudaGetSymbolAddress((void**)&xc, g_xc);
    cudaGetSymbolAddress((void**)&dbc, g_dbc);
    cudaGetSymbolAddress((void**)&dt, g_dt);
    cudaGetSymbolAddress((void**)&cP, g_cP);
    cudaGetSymbolAddress((void**)&cE, g_cE);
    cudaGetSymbolAddress((void**)&Hi, g_hinit);
    cudaGetSymbolAddress((void**)&y, g_y);

    cudaEventRecord(evA, 0);
    cudaStreamWaitEvent(s1, evA, 0);
    cudaStreamWaitEvent(s2, evA, 0);

    k_pv<<<64,256,0,s1>>>(x, pv, sacc);
    cudaEventRecord(evPV, s1);

    k_transpose<<<dim3(128,4,4),dim3(32,8),0,s2>>>(x, xT);
    cudaEventRecord(evT, s2);

    k_conv1<<<512,256>>>(x, conv1_w, conv1_b, feat, casum);
    k_ca<<<4,256>>>(casum, ca1_w, ca2_w, ca);
    cudaStreamWaitEvent(0, evPV, 0);
    k_score2<<<512,256>>>(feat, ca, conv2_w, conv2_b, head_w, sacc);
    k_sort<<<4,256>>>(sacc, pv, head_b, order);
    cudaStreamWaitEvent(0, evT, 0);
    k_gather_ln<<<2048,256>>>(xT, pe, order, norm_g, norm_b, x1n);
    gemm_tf32<<<dim3(4,128),256>>>(x1n, in_proj_w, xz, 16384, 512, 128, 256, 0, 0);
    k_xproj<<<512,256,88000>>>(xz, conv1d_w, conv1d_b, x_proj_w, dt_proj_w,
                               dt_proj_b, xc, dbc, dt);
    k_scan1<<<512,128>>>(dt, xc, dbc, A_log, cP, cE);
    k_scan2<<<64,256>>>(cP, cE, Hi);
    k_scan3<<<512,128>>>(dt, xc, dbc, A_log, Hi, xz, D_, y);
    gemm_tf32<<<dim3(1,128),256>>>(y, out_proj_w, out, 16384, 128, 256, 1<<30,
                                   order, 1);
}